// round 11
// baseline (speedup 1.0000x reference)
#include <cuda_runtime.h>
#include <cuda_bf16.h>
#include <mma.h>
#include <cmath>

using namespace nvcuda;

#define LL     1024
#define EE     768
#define PPD    128
#define HH     16
#define HDIM   48
#define NDEPTH 8
#define MLPD   3072
#define NFREQ  256

// ---------------- device-global scratch (no allocations allowed) ----------------
__device__ __align__(16) float g_x[LL*EE];
__device__ __align__(16) float g_h[LL*EE];
__device__ __align__(16) float g_qkv[LL*3*EE];
__device__ __align__(16) float g_y[LL*EE];
__device__ __align__(16) float g_mlp[LL*MLPD];
__device__ __align__(16) __nv_bfloat16 g_bh[(size_t)HH*LL*LL];   // 32 MB, [h][l][m]
__device__ float g_cpre[EE];
__device__ float g_cs[EE];
__device__ float g_ada[NDEPTH*6*EE + 2*EE];
__device__ float g_Apw[HH*PPD];
__device__ float g_Spw[HH];
__device__ float g_Cpw[HH];

__device__ __forceinline__ void cp16(float* s, const float* g) {
    unsigned sa = (unsigned)__cvta_generic_to_shared(s);
    asm volatile("cp.async.cg.shared.global [%0], [%1], 16;\n" :: "r"(sa), "l"(g));
}
#define CP_COMMIT() asm volatile("cp.async.commit_group;\n" ::: "memory")
#define CP_WAIT0()  asm volatile("cp.async.wait_group 0;\n" ::: "memory")
#define CP_WAIT1()  asm volatile("cp.async.wait_group 1;\n" ::: "memory")

// ---------------- init ----------------
__global__ void k_copy(const float* __restrict__ z) {
    int i = blockIdx.x*1024 + threadIdx.x;
    g_x[i] = z[i];
}

__global__ void k_prep(const float* __restrict__ g, const float* __restrict__ beta,
                       const float* __restrict__ w) {
    const int p = threadIdx.x; // 128
    for (int h = 0; h < HH; h++)
        g_Apw[h*PPD + p] = g[p] * w[h*PPD + p];
    if (p < HH) {
        float s = 0.f, c = 0.f;
        for (int q = 0; q < PPD; q++) {
            s += g[q]    * w[p*PPD + q];
            c += beta[q] * w[p*PPD + q];
        }
        g_Spw[p] = s; g_Cpw[p] = c;
    }
}

// ---------------- bias LN + head projection: 512 MB read, one thread per row ----------------
__global__ void __launch_bounds__(256) k_bias(const float* __restrict__ bias) {
    __shared__ __align__(16) float sA[HH*PPD];
    __shared__ float sSh[HH], sCh[HH];
    const int tid = threadIdx.x;
    for (int i = tid; i < HH*PPD; i += 256) sA[i] = g_Apw[i];
    if (tid < HH) { sSh[tid] = g_Spw[tid]; sCh[tid] = g_Cpw[tid]; }
    __syncthreads();
    const int row = blockIdx.x*256 + tid;      // row = l*1024 + m
    const float* xr = bias + (size_t)row*PPD;
    float acc[HH];
#pragma unroll
    for (int h = 0; h < HH; h++) acc[h] = 0.f;
    float s = 0.f, ss = 0.f;
#pragma unroll
    for (int ch = 0; ch < 4; ch++) {
        float4 xv[8];
#pragma unroll
        for (int j = 0; j < 8; j++) xv[j] = *(const float4*)&xr[ch*32 + j*4];
#pragma unroll
        for (int j = 0; j < 8; j++) {
            s  += xv[j].x + xv[j].y + xv[j].z + xv[j].w;
            ss += xv[j].x*xv[j].x + xv[j].y*xv[j].y + xv[j].z*xv[j].z + xv[j].w*xv[j].w;
        }
#pragma unroll
        for (int h = 0; h < HH; h++) {
            const float* ar = &sA[h*PPD + ch*32];
            float a0 = 0.f;
#pragma unroll
            for (int j = 0; j < 8; j++) {
                float4 av = *(const float4*)&ar[j*4];
                a0 += xv[j].x*av.x + xv[j].y*av.y + xv[j].z*av.z + xv[j].w*av.w;
            }
            acc[h] += a0;
        }
    }
    const float mu   = s * (1.0f/PPD);
    const float rstd = rsqrtf(ss*(1.0f/PPD) - mu*mu + 1e-6f);
    const int l = row >> 10, m = row & 1023;
#pragma unroll
    for (int h = 0; h < HH; h++) {
        float v = rstd*(acc[h] - mu*sSh[h]) + sCh[h];
        g_bh[((size_t)h << 20) + ((size_t)l << 10) + m] = __float2bfloat16(v);
    }
}

// ---------------- time embedding chain ----------------
__global__ void __launch_bounds__(256) k_time1(const float* __restrict__ t,
                                               const float* __restrict__ t0_w,
                                               const float* __restrict__ t0_b) {
    __shared__ float emb[NFREQ];
    const int tid = threadIdx.x;  // 256
    {
        int i = tid & 127;
        float f   = expf(-9.210340371976184f * (float)i / 128.0f);
        float arg = t[0] * f;
        emb[tid] = (tid < 128) ? cosf(arg) : sinf(arg);
    }
    __syncthreads();
    const int warp = tid >> 5, lane = tid & 31;
    const int j = blockIdx.x*8 + warp;
    const float* w = t0_w + (size_t)j*NFREQ;
    float acc = 0.f;
#pragma unroll
    for (int i = 0; i < 8; i++) acc += emb[lane + i*32] * w[lane + i*32];
#pragma unroll
    for (int o = 16; o > 0; o >>= 1) acc += __shfl_xor_sync(0xffffffffu, acc, o);
    if (lane == 0) {
        float a = acc + t0_b[j];
        g_cpre[j] = a / (1.f + expf(-a));
    }
}

__global__ void __launch_bounds__(256) k_time2(const float* __restrict__ t2_w,
                                               const float* __restrict__ t2_b) {
    __shared__ float cp[EE];
    const int tid = threadIdx.x;
    for (int i = tid; i < EE; i += 256) cp[i] = g_cpre[i];
    __syncthreads();
    const int warp = tid >> 5, lane = tid & 31;
    const int j = blockIdx.x*8 + warp;
    const float* w = t2_w + (size_t)j*EE;
    float acc = 0.f;
#pragma unroll
    for (int i = 0; i < 24; i++) acc += cp[lane + i*32] * w[lane + i*32];
#pragma unroll
    for (int o = 16; o > 0; o >>= 1) acc += __shfl_xor_sync(0xffffffffu, acc, o);
    if (lane == 0) {
        float a = acc + t2_b[j];
        g_cs[j] = a / (1.f + expf(-a));
    }
}

// all adaLN vectors, one warp per row
__global__ void k_ada(const float* __restrict__ aw, const float* __restrict__ ab,
                      const float* __restrict__ fw, const float* __restrict__ fb) {
    const int gw   = (blockIdx.x*blockDim.x + threadIdx.x) >> 5;
    const int lane = threadIdx.x & 31;
    const int total = NDEPTH*6*EE + 2*EE;
    if (gw >= total) return;
    const float* wrow; float b;
    if (gw < NDEPTH*6*EE) { wrow = aw + (size_t)gw*EE; b = ab[gw]; }
    else { int r = gw - NDEPTH*6*EE; wrow = fw + (size_t)r*EE; b = fb[r]; }
    float acc = 0.f;
    for (int i = lane; i < EE; i += 32) acc += g_cs[i]*wrow[i];
#pragma unroll
    for (int o = 16; o > 0; o >>= 1) acc += __shfl_xor_sync(0xffffffffu, acc, o);
    if (lane == 0) g_ada[gw] = acc + b;
}

// ---------------- LayerNorm + adaLN modulation ----------------
__global__ void __launch_bounds__(256) k_lnmod(const float* __restrict__ x,
                                               int sh_off, int sc_off,
                                               float* __restrict__ out) {
    const int row = blockIdx.x, tid = threadIdx.x;
    const float* xr = x + (size_t)row*EE;
    float v0 = xr[tid], v1 = xr[tid+256], v2 = xr[tid+512];
    float s  = v0 + v1 + v2;
    float ss = v0*v0 + v1*v1 + v2*v2;
    __shared__ float rs[8], rss[8];
#pragma unroll
    for (int o = 16; o > 0; o >>= 1) {
        s  += __shfl_xor_sync(0xffffffffu, s,  o);
        ss += __shfl_xor_sync(0xffffffffu, ss, o);
    }
    if ((tid & 31) == 0) { rs[tid>>5] = s; rss[tid>>5] = ss; }
    __syncthreads();
    float st = 0.f, sst = 0.f;
#pragma unroll
    for (int i = 0; i < 8; i++) { st += rs[i]; sst += rss[i]; }
    const float mu   = st * (1.0f/EE);
    const float rstd = rsqrtf(sst*(1.0f/EE) - mu*mu + 1e-6f);
    const float* sh = g_ada + sh_off;
    const float* sc = g_ada + sc_off;
    float* orow = out + (size_t)row*EE;
    orow[tid]     = (v0-mu)*rstd*(1.f+sc[tid])     + sh[tid];
    orow[tid+256] = (v1-mu)*rstd*(1.f+sc[tid+256]) + sh[tid+256];
    orow[tid+512] = (v2-mu)*rstd*(1.f+sc[tid+512]) + sh[tid+512];
}

// ---------------- tf32 wmma GEMM, cp.async 3-stage pipeline ----------------
// C(MxN) = A(MxK) @ W(NxK)^T. Warp tile 32x64 (BN>=128) or 32x32.
// EPI 0: out = acc+bias    EPI 1: out += g_ada[g_off+n]*(acc+bias)    EPI 2: out = gelu_tanh(acc+bias)
#define GBK 32
#define GLD 36

template<int BM, int BN, int T, int AF4, int BF4>
__device__ __forceinline__ void g_issue(float* stage, const float* A, const float* W,
                                        int m0, int n0, int K, int k0, int tid) {
    float* sA = stage;
    float* sB = stage + BM*GLD;
#pragma unroll
    for (int i = 0; i < AF4; i++) {
        int f = tid + i*T;
        cp16(&sA[(f>>3)*GLD + ((f&7)<<2)], &A[(size_t)(m0 + (f>>3))*K + k0 + ((f&7)<<2)]);
    }
#pragma unroll
    for (int i = 0; i < BF4; i++) {
        int f = tid + i*T;
        cp16(&sB[(f>>3)*GLD + ((f&7)<<2)], &W[(size_t)(n0 + (f>>3))*K + k0 + ((f&7)<<2)]);
    }
    CP_COMMIT();
}

template<int EPI, int BM, int BN>
__global__ void __launch_bounds__((BM/32)*(BN/((BN>=128)?64:32))*32) k_gemm(
        const float* __restrict__ A, const float* __restrict__ W,
        const float* __restrict__ bias, int g_off,
        float* __restrict__ out, int M, int N, int K) {
    constexpr int WTN = (BN >= 128) ? 64 : 32;
    constexpr int WMC = BM/32, WNC = BN/WTN, NW = WMC*WNC, T = NW*32;
    constexpr int NJ  = WTN/16;
    constexpr int STG = (BM+BN)*GLD;
    constexpr int AF4 = BM*8/T, BF4 = BN*8/T;
    constexpr int CLD = WTN + 4;

    extern __shared__ __align__(16) float smem[];
    const int tid = threadIdx.x, warp = tid >> 5, lane = tid & 31;
    const int wm = warp % WMC, wn = warp / WMC;
    const int m0 = blockIdx.y * BM;
    const int n0 = blockIdx.x * BN;

    wmma::fragment<wmma::accumulator,16,16,8,float> cf[2][NJ];
#pragma unroll
    for (int i = 0; i < 2; i++)
#pragma unroll
        for (int j = 0; j < NJ; j++) wmma::fill_fragment(cf[i][j], 0.0f);

    const int nch = K / GBK;
    g_issue<BM,BN,T,AF4,BF4>(smem,          A, W, m0, n0, K, 0,   tid);
    g_issue<BM,BN,T,AF4,BF4>(smem + STG,    A, W, m0, n0, K, GBK, tid);

    for (int ch = 0; ch < nch; ch++) {
        if (ch == nch-1) { CP_WAIT0(); } else { CP_WAIT1(); }
        __syncthreads();
        float* sA = smem + (ch % 3)*STG;
        float* sB = sA + BM*GLD;
#pragma unroll
        for (int kk = 0; kk < 4; kk++) {
            wmma::fragment<wmma::matrix_a,16,16,8,wmma::precision::tf32,wmma::row_major> af[2];
            wmma::fragment<wmma::matrix_b,16,16,8,wmma::precision::tf32,wmma::col_major> bf[NJ];
#pragma unroll
            for (int i = 0; i < 2; i++) {
                wmma::load_matrix_sync(af[i], sA + (wm*32 + i*16)*GLD + kk*8, GLD);
#pragma unroll
                for (int q = 0; q < af[i].num_elements; q++) af[i].x[q] = wmma::__float_to_tf32(af[i].x[q]);
            }
#pragma unroll
            for (int j = 0; j < NJ; j++) {
                wmma::load_matrix_sync(bf[j], sB + (wn*WTN + j*16)*GLD + kk*8, GLD);
#pragma unroll
                for (int q = 0; q < bf[j].num_elements; q++) bf[j].x[q] = wmma::__float_to_tf32(bf[j].x[q]);
            }
#pragma unroll
            for (int i = 0; i < 2; i++)
#pragma unroll
                for (int j = 0; j < NJ; j++) wmma::mma_sync(cf[i][j], af[i], bf[j], cf[i][j]);
        }
        if (ch + 2 < nch)
            g_issue<BM,BN,T,AF4,BF4>(smem + ((ch+2) % 3)*STG, A, W, m0, n0, K, (ch+2)*GBK, tid);
    }
    __syncthreads();
    // epilogue: stage per-warp 32 x WTN tile in smem
    float* cbuf = smem + warp*(32*CLD);
#pragma unroll
    for (int i = 0; i < 2; i++)
#pragma unroll
        for (int j = 0; j < NJ; j++)
            wmma::store_matrix_sync(cbuf + (i*16)*CLD + j*16, cf[i][j], CLD, wmma::mem_row_major);
    __syncwarp();
    const int nbase = n0 + wn*WTN;
    float bv[WTN/32], gv[WTN/32];
#pragma unroll
    for (int cc = 0; cc < WTN/32; cc++) {
        int ncol = nbase + cc*32 + lane;
        bv[cc] = bias ? bias[ncol] : 0.0f;
        gv[cc] = (EPI == 1) ? g_ada[g_off + ncol] : 0.0f;
    }
#pragma unroll 4
    for (int r = 0; r < 32; r++) {
#pragma unroll
        for (int cc = 0; cc < WTN/32; cc++) {
            float v = cbuf[r*CLD + cc*32 + lane] + bv[cc];
            size_t oi = (size_t)(m0 + wm*32 + r)*N + nbase + cc*32 + lane;
            if (EPI == 0) {
                out[oi] = v;
            } else if (EPI == 1) {
                out[oi] = out[oi] + gv[cc] * v;
            } else {
                float tn = tanhf(0.7978845608028654f*(v + 0.044715f*v*v*v));
                out[oi] = 0.5f*v*(1.0f + tn);
            }
        }
    }
}

// ---------------- fused flash attention: one CTA per (q-tile 64, head), KV tile 64 ----------------
#define FLD  48
#define FLDS 68

__global__ void __launch_bounds__(128) k_flash() {
    extern __shared__ __align__(16) float fs[];
    float* sQ = fs;                 // 64 x 48
    float* sK = fs + 3072;          // 64 x 48
    float* sV = fs + 6144;          // 64 x 48
    float* sO = fs + 9216;          // 64 x 48
    float* sS = fs + 12288;         // 64 x 68 (64 cols used)
    float* sM = fs + 16640;         // 64
    float* sL = fs + 16704;         // 64

    const int tid  = threadIdx.x;   // 128
    const int warp = tid >> 5;
    const int qt = blockIdx.x, hh = blockIdx.y;
    const int l0 = qt*64;
    const float scale = 0.14433756729740643f;   // 48^-0.5
    const int rr = tid >> 1, hf = tid & 1;

    // load scaled Q tile (64 x 48)
#pragma unroll
    for (int i = 0; i < 6; i++) {
        int e = tid + i*128;
        int r = e/12, c4 = e%12;
        float4 v = *(const float4*)&g_qkv[(size_t)(l0+r)*(3*EE) + hh*144 + c4*4];
        v.x *= scale; v.y *= scale; v.z *= scale; v.w *= scale;
        *(float4*)&sQ[r*FLD + c4*4] = v;
    }
    for (int i = tid; i < 64*FLD; i += 128) sO[i] = 0.0f;
    if (tid < 64) { sM[tid] = -1e30f; sL[tid] = 0.0f; }

    // register prefetch of K/V tile 0 (64 rows)
    float4 pk[6], pv[6];
#pragma unroll
    for (int i = 0; i < 6; i++) {
        int e = tid + i*128;
        int r = e/12, c4 = e%12;
        pk[i] = *(const float4*)&g_qkv[(size_t)r*(3*EE) + hh*144 + 48 + c4*4];
        pv[i] = *(const float4*)&g_qkv[(size_t)r*(3*EE) + hh*144 + 96 + c4*4];
    }

    for (int mt = 0; mt < 16; mt++) {
        const int m0 = mt*64;
        __syncthreads();               // protects sK/sV reuse (+ init on iter 0)
#pragma unroll
        for (int i = 0; i < 6; i++) {
            int e = tid + i*128;
            int r = e/12, c4 = e%12;
            *(float4*)&sK[r*FLD + c4*4] = pk[i];
            *(float4*)&sV[r*FLD + c4*4] = pv[i];
        }
        __syncthreads();
        // prefetch next tile (overlaps with S/softmax/PV)
        if (mt < 15) {
            const int mn = m0 + 64;
#pragma unroll
            for (int i = 0; i < 6; i++) {
                int e = tid + i*128;
                int r = e/12, c4 = e%12;
                pk[i] = *(const float4*)&g_qkv[(size_t)(mn+r)*(3*EE) + hh*144 + 48 + c4*4];
                pv[i] = *(const float4*)&g_qkv[(size_t)(mn+r)*(3*EE) + hh*144 + 96 + c4*4];
            }
        }
        // S = Q @ K^T : warp handles rows warp*16..+15, cols 0..63
#pragma unroll
        for (int nt = 0; nt < 4; nt++) {
            wmma::fragment<wmma::accumulator,16,16,8,float> sc;
            wmma::fill_fragment(sc, 0.0f);
#pragma unroll
            for (int k = 0; k < 6; k++) {
                wmma::fragment<wmma::matrix_a,16,16,8,wmma::precision::tf32,wmma::row_major> af;
                wmma::fragment<wmma::matrix_b,16,16,8,wmma::precision::tf32,wmma::col_major> bf;
                wmma::load_matrix_sync(af, sQ + warp*16*FLD + k*8, FLD);
                wmma::load_matrix_sync(bf, sK + nt*16*FLD + k*8, FLD);
#pragma unroll
                for (int q = 0; q < af.num_elements; q++) af.x[q] = wmma::__float_to_tf32(af.x[q]);
#pragma unroll
                for (int q = 0; q < bf.num_elements; q++) bf.x[q] = wmma::__float_to_tf32(bf.x[q]);
                wmma::mma_sync(sc, af, bf, sc);
            }
            wmma::store_matrix_sync(sS + warp*16*FLDS + nt*16, sc, FLDS, wmma::mem_row_major);
        }
        __syncthreads();
        // bias add + online softmax: 2 threads per row, 32 cols each
        {
            const int c0 = hf*32;
            const __nv_bfloat16* bp = &g_bh[((size_t)hh << 20) + ((size_t)(l0+rr) << 10) + m0 + c0];
            float* srow = sS + rr*FLDS + c0;
            float v[32];
            float mloc = -1e30f;
#pragma unroll
            for (int c = 0; c < 32; c++) {
                v[c] = srow[c] + __bfloat162float(bp[c]);
                mloc = fmaxf(mloc, v[c]);
            }
            mloc = fmaxf(mloc, __shfl_xor_sync(0xffffffffu, mloc, 1));
            float mprev = sM[rr];
            float mnew  = fmaxf(mprev, mloc);
            float sum = 0.f;
#pragma unroll
            for (int c = 0; c < 32; c++) {
                float p = __expf(v[c] - mnew);
                srow[c] = p;
                sum += p;
            }
            sum += __shfl_xor_sync(0xffffffffu, sum, 1);
            float factor = __expf(mprev - mnew);
            if (hf == 0) { sM[rr] = mnew; sL[rr] = sL[rr]*factor + sum; }
            float* orow = sO + rr*FLD + hf*24;
#pragma unroll
            for (int c = 0; c < 24; c++) orow[c] *= factor;
        }
        __syncthreads();
        // O += P(64x64) @ V(64x48)
        {
            wmma::fragment<wmma::matrix_a,16,16,8,wmma::precision::tf32,wmma::row_major> pa[8];
#pragma unroll
            for (int kk = 0; kk < 8; kk++) {
                wmma::load_matrix_sync(pa[kk], sS + warp*16*FLDS + kk*8, FLDS);
#pragma unroll
                for (int q = 0; q < pa[kk].num_elements; q++) pa[kk].x[q] = wmma::__float_to_tf32(pa[kk].x[q]);
            }
#pragma unroll
            for (int j = 0; j < 3; j++) {
                wmma::fragment<wmma::accumulator,16,16,8,float> of;
                wmma::load_matrix_sync(of, sO + warp*16*FLD + j*16, FLD, wmma::mem_row_major);
#pragma unroll
                for (int kk = 0; kk < 8; kk++) {
                    wmma::fragment<wmma::matrix_b,16,16,8,wmma::precision::tf32,wmma::row_major> vb;
                    wmma::load_matrix_sync(vb, sV + kk*8*FLD + j*16, FLD);
#pragma unroll
                    for (int q = 0; q < vb.num_elements; q++) vb.x[q] = wmma::__float_to_tf32(vb.x[q]);
                    wmma::mma_sync(of, pa[kk], vb, of);
                }
                wmma::store_matrix_sync(sO + warp*16*FLD + j*16, of, FLD, wmma::mem_row_major);
            }
        }
    }
    __syncthreads();
    // normalize + write y[l, h*48+c]
    {
        float inv = 1.0f / sL[rr];
        const float* orow = sO + rr*FLD + hf*24;
        float* dst = g_y + (size_t)(l0+rr)*EE + hh*HDIM + hf*24;
#pragma unroll
        for (int c = 0; c < 24; c++) dst[c] = orow[c]*inv;
    }
}

// ---------------- driver ----------------
static const int SM_BIG   = 3*(128+128)*GLD*4;   // 110592 B (3-stage 128x128)
static const int SM_SMALL = 3*(64+64)*GLD*4;     //  55296 B (3-stage 64x64)
static const int SM_FLASH = 16768*4;             //  67072 B

extern "C" void kernel_launch(void* const* d_in, const int* in_sizes, int n_in,
                              void* d_out, int out_size) {
    const float* z    = (const float*)d_in[0];
    const float* t    = (const float*)d_in[1];
    const float* bias = (const float*)d_in[2];
    const float* ln_g = (const float*)d_in[3];
    const float* ln_b = (const float*)d_in[4];
    const float* p2sw = (const float*)d_in[5];
    const float* t0w  = (const float*)d_in[6];
    const float* t0b  = (const float*)d_in[7];
    const float* t2w  = (const float*)d_in[8];
    const float* t2b  = (const float*)d_in[9];
    const float* pw   = (const float*)d_in[10];
    const float* ow   = (const float*)d_in[11];
    const float* ob   = (const float*)d_in[12];
    const float* aw   = (const float*)d_in[13];
    const float* ab   = (const float*)d_in[14];
    const float* f1w  = (const float*)d_in[15];
    const float* f1b  = (const float*)d_in[16];
    const float* f2w  = (const float*)d_in[17];
    const float* f2b  = (const float*)d_in[18];
    const float* faw  = (const float*)d_in[19];
    const float* fab  = (const float*)d_in[20];
    const float* fw   = (const float*)d_in[21];
    const float* fb   = (const float*)d_in[22];

    float *px, *ph, *pq, *py, *pm;
    cudaGetSymbolAddress((void**)&px, g_x);
    cudaGetSymbolAddress((void**)&ph, g_h);
    cudaGetSymbolAddress((void**)&pq, g_qkv);
    cudaGetSymbolAddress((void**)&py, g_y);
    cudaGetSymbolAddress((void**)&pm, g_mlp);

    cudaFuncSetAttribute(k_gemm<0,128,128>, cudaFuncAttributeMaxDynamicSharedMemorySize, SM_BIG);
    cudaFuncSetAttribute(k_gemm<2,128,128>, cudaFuncAttributeMaxDynamicSharedMemorySize, SM_BIG);
    cudaFuncSetAttribute(k_gemm<0,64,64>,   cudaFuncAttributeMaxDynamicSharedMemorySize, SM_SMALL);
    cudaFuncSetAttribute(k_gemm<1,64,64>,   cudaFuncAttributeMaxDynamicSharedMemorySize, SM_SMALL);
    cudaFuncSetAttribute(k_flash,           cudaFuncAttributeMaxDynamicSharedMemorySize, SM_FLASH);

    k_copy<<<768, 1024>>>(z);
    k_prep<<<1, 128>>>(ln_g, ln_b, p2sw);
    k_bias<<<4096, 256>>>(bias);
    k_time1<<<96, 256>>>(t, t0w, t0b);
    k_time2<<<96, 256>>>(t2w, t2b);
    k_ada<<<4800, 256>>>(aw, ab, faw, fab);

    for (int d = 0; d < NDEPTH; d++) {
        const int base = d*6*EE;
        // attention branch
        k_lnmod<<<1024, 256>>>(px, base, base + EE, ph);
        k_gemm<0,128,128><<<dim3(18, 8), 256, SM_BIG>>>(ph, pw + (size_t)d*3*EE*EE, nullptr, 0,
                                                        pq, LL, 3*EE, EE);
        k_flash<<<dim3(16, 16), 128, SM_FLASH>>>();
        k_gemm<1,64,64><<<dim3(12, 16), 128, SM_SMALL>>>(py, ow + (size_t)d*EE*EE, ob + d*EE, base + 2*EE,
                                                         px, LL, EE, EE);
        // MLP branch
        k_lnmod<<<1024, 256>>>(px, base + 3*EE, base + 4*EE, ph);
        k_gemm<2,128,128><<<dim3(24, 8), 256, SM_BIG>>>(ph, f1w + (size_t)d*MLPD*EE, f1b + d*MLPD, 0,
                                                        pm, LL, MLPD, EE);
        k_gemm<1,64,64><<<dim3(12, 16), 128, SM_SMALL>>>(pm, f2w + (size_t)d*EE*MLPD, f2b + d*EE, base + 5*EE,
                                                         px, LL, EE, MLPD);
    }
    // final
    const int foff = NDEPTH*6*EE;
    k_lnmod<<<1024, 256>>>(px, foff, foff + EE, ph);
    k_gemm<0,64,64><<<dim3(12, 16), 128, SM_SMALL>>>(ph, fw, fb, 0, (float*)d_out, LL, EE, EE);
}

// round 12
// speedup vs baseline: 1.0035x; 1.0035x over previous
#include <cuda_runtime.h>
#include <cuda_bf16.h>
#include <mma.h>
#include <cmath>

using namespace nvcuda;

#define LL     1024
#define EE     768
#define PPD    128
#define HH     16
#define HDIM   48
#define NDEPTH 8
#define MLPD   3072
#define NFREQ  256

// ---------------- device-global scratch (no allocations allowed) ----------------
__device__ __align__(16) float g_x[LL*EE];
__device__ __align__(16) float g_h[LL*EE];
__device__ __align__(16) float g_qkv[LL*3*EE];
__device__ __align__(16) float g_y[LL*EE];
__device__ __align__(16) float g_mlp[LL*MLPD];
__device__ __align__(16) __nv_bfloat16 g_bh[(size_t)HH*LL*LL];   // 32 MB, [h][l][m]
__device__ float g_cpre[EE];
__device__ float g_cs[EE];
__device__ float g_ada[NDEPTH*6*EE + 2*EE];
__device__ float g_Apw[HH*PPD];
__device__ float g_Spw[HH];
__device__ float g_Cpw[HH];

__device__ __forceinline__ void cp16(float* s, const float* g) {
    unsigned sa = (unsigned)__cvta_generic_to_shared(s);
    asm volatile("cp.async.cg.shared.global [%0], [%1], 16;\n" :: "r"(sa), "l"(g));
}
#define CP_COMMIT() asm volatile("cp.async.commit_group;\n" ::: "memory")
#define CP_WAIT0()  asm volatile("cp.async.wait_group 0;\n" ::: "memory")
#define CP_WAIT1()  asm volatile("cp.async.wait_group 1;\n" ::: "memory")

// ---------------- init ----------------
__global__ void k_copy(const float* __restrict__ z) {
    int i = blockIdx.x*1024 + threadIdx.x;
    g_x[i] = z[i];
}

__global__ void k_prep(const float* __restrict__ g, const float* __restrict__ beta,
                       const float* __restrict__ w) {
    const int p = threadIdx.x; // 128
    for (int h = 0; h < HH; h++)
        g_Apw[h*PPD + p] = g[p] * w[h*PPD + p];
    if (p < HH) {
        float s = 0.f, c = 0.f;
        for (int q = 0; q < PPD; q++) {
            s += g[q]    * w[p*PPD + q];
            c += beta[q] * w[p*PPD + q];
        }
        g_Spw[p] = s; g_Cpw[p] = c;
    }
}

// ---------------- bias LN + head projection: 512 MB read, one thread per row ----------------
__global__ void __launch_bounds__(256) k_bias(const float* __restrict__ bias) {
    __shared__ __align__(16) float sA[HH*PPD];
    __shared__ float sSh[HH], sCh[HH];
    const int tid = threadIdx.x;
    for (int i = tid; i < HH*PPD; i += 256) sA[i] = g_Apw[i];
    if (tid < HH) { sSh[tid] = g_Spw[tid]; sCh[tid] = g_Cpw[tid]; }
    __syncthreads();
    const int row = blockIdx.x*256 + tid;      // row = l*1024 + m
    const float* xr = bias + (size_t)row*PPD;
    float acc[HH];
#pragma unroll
    for (int h = 0; h < HH; h++) acc[h] = 0.f;
    float s = 0.f, ss = 0.f;
#pragma unroll
    for (int ch = 0; ch < 4; ch++) {
        float4 xv[8];
#pragma unroll
        for (int j = 0; j < 8; j++) xv[j] = *(const float4*)&xr[ch*32 + j*4];
#pragma unroll
        for (int j = 0; j < 8; j++) {
            s  += xv[j].x + xv[j].y + xv[j].z + xv[j].w;
            ss += xv[j].x*xv[j].x + xv[j].y*xv[j].y + xv[j].z*xv[j].z + xv[j].w*xv[j].w;
        }
#pragma unroll
        for (int h = 0; h < HH; h++) {
            const float* ar = &sA[h*PPD + ch*32];
            float a0 = 0.f;
#pragma unroll
            for (int j = 0; j < 8; j++) {
                float4 av = *(const float4*)&ar[j*4];
                a0 += xv[j].x*av.x + xv[j].y*av.y + xv[j].z*av.z + xv[j].w*av.w;
            }
            acc[h] += a0;
        }
    }
    const float mu   = s * (1.0f/PPD);
    const float rstd = rsqrtf(ss*(1.0f/PPD) - mu*mu + 1e-6f);
    const int l = row >> 10, m = row & 1023;
#pragma unroll
    for (int h = 0; h < HH; h++) {
        float v = rstd*(acc[h] - mu*sSh[h]) + sCh[h];
        g_bh[((size_t)h << 20) + ((size_t)l << 10) + m] = __float2bfloat16(v);
    }
}

// ---------------- time embedding chain ----------------
__global__ void __launch_bounds__(256) k_time1(const float* __restrict__ t,
                                               const float* __restrict__ t0_w,
                                               const float* __restrict__ t0_b) {
    __shared__ float emb[NFREQ];
    const int tid = threadIdx.x;  // 256
    {
        int i = tid & 127;
        float f   = expf(-9.210340371976184f * (float)i / 128.0f);
        float arg = t[0] * f;
        emb[tid] = (tid < 128) ? cosf(arg) : sinf(arg);
    }
    __syncthreads();
    const int warp = tid >> 5, lane = tid & 31;
    const int j = blockIdx.x*8 + warp;
    const float* w = t0_w + (size_t)j*NFREQ;
    float acc = 0.f;
#pragma unroll
    for (int i = 0; i < 8; i++) acc += emb[lane + i*32] * w[lane + i*32];
#pragma unroll
    for (int o = 16; o > 0; o >>= 1) acc += __shfl_xor_sync(0xffffffffu, acc, o);
    if (lane == 0) {
        float a = acc + t0_b[j];
        g_cpre[j] = a / (1.f + expf(-a));
    }
}

__global__ void __launch_bounds__(256) k_time2(const float* __restrict__ t2_w,
                                               const float* __restrict__ t2_b) {
    __shared__ float cp[EE];
    const int tid = threadIdx.x;
    for (int i = tid; i < EE; i += 256) cp[i] = g_cpre[i];
    __syncthreads();
    const int warp = tid >> 5, lane = tid & 31;
    const int j = blockIdx.x*8 + warp;
    const float* w = t2_w + (size_t)j*EE;
    float acc = 0.f;
#pragma unroll
    for (int i = 0; i < 24; i++) acc += cp[lane + i*32] * w[lane + i*32];
#pragma unroll
    for (int o = 16; o > 0; o >>= 1) acc += __shfl_xor_sync(0xffffffffu, acc, o);
    if (lane == 0) {
        float a = acc + t2_b[j];
        g_cs[j] = a / (1.f + expf(-a));
    }
}

// all adaLN vectors, one warp per row
__global__ void k_ada(const float* __restrict__ aw, const float* __restrict__ ab,
                      const float* __restrict__ fw, const float* __restrict__ fb) {
    const int gw   = (blockIdx.x*blockDim.x + threadIdx.x) >> 5;
    const int lane = threadIdx.x & 31;
    const int total = NDEPTH*6*EE + 2*EE;
    if (gw >= total) return;
    const float* wrow; float b;
    if (gw < NDEPTH*6*EE) { wrow = aw + (size_t)gw*EE; b = ab[gw]; }
    else { int r = gw - NDEPTH*6*EE; wrow = fw + (size_t)r*EE; b = fb[r]; }
    float acc = 0.f;
    for (int i = lane; i < EE; i += 32) acc += g_cs[i]*wrow[i];
#pragma unroll
    for (int o = 16; o > 0; o >>= 1) acc += __shfl_xor_sync(0xffffffffu, acc, o);
    if (lane == 0) g_ada[gw] = acc + b;
}

// ---------------- LayerNorm + adaLN modulation ----------------
__global__ void __launch_bounds__(256) k_lnmod(const float* __restrict__ x,
                                               int sh_off, int sc_off,
                                               float* __restrict__ out) {
    const int row = blockIdx.x, tid = threadIdx.x;
    const float* xr = x + (size_t)row*EE;
    float v0 = xr[tid], v1 = xr[tid+256], v2 = xr[tid+512];
    float s  = v0 + v1 + v2;
    float ss = v0*v0 + v1*v1 + v2*v2;
    __shared__ float rs[8], rss[8];
#pragma unroll
    for (int o = 16; o > 0; o >>= 1) {
        s  += __shfl_xor_sync(0xffffffffu, s,  o);
        ss += __shfl_xor_sync(0xffffffffu, ss, o);
    }
    if ((tid & 31) == 0) { rs[tid>>5] = s; rss[tid>>5] = ss; }
    __syncthreads();
    float st = 0.f, sst = 0.f;
#pragma unroll
    for (int i = 0; i < 8; i++) { st += rs[i]; sst += rss[i]; }
    const float mu   = st * (1.0f/EE);
    const float rstd = rsqrtf(sst*(1.0f/EE) - mu*mu + 1e-6f);
    const float* sh = g_ada + sh_off;
    const float* sc = g_ada + sc_off;
    float* orow = out + (size_t)row*EE;
    orow[tid]     = (v0-mu)*rstd*(1.f+sc[tid])     + sh[tid];
    orow[tid+256] = (v1-mu)*rstd*(1.f+sc[tid+256]) + sh[tid+256];
    orow[tid+512] = (v2-mu)*rstd*(1.f+sc[tid+512]) + sh[tid+512];
}

// ---------------- tf32 wmma GEMM, cp.async 3-stage pipeline ----------------
// C(MxN) = A(MxK) @ W(NxK)^T. Warp tile 32x64 (BN>=128) or 32x32.
// EPI 0: out = acc+bias    EPI 1: out += g_ada[g_off+n]*(acc+bias)    EPI 2: out = gelu_tanh(acc+bias)
#define GBK 32
#define GLD 36

template<int BM, int BN, int T, int AF4, int BF4>
__device__ __forceinline__ void g_issue(float* stage, const float* A, const float* W,
                                        int m0, int n0, int K, int k0, int tid) {
    float* sA = stage;
    float* sB = stage + BM*GLD;
#pragma unroll
    for (int i = 0; i < AF4; i++) {
        int f = tid + i*T;
        cp16(&sA[(f>>3)*GLD + ((f&7)<<2)], &A[(size_t)(m0 + (f>>3))*K + k0 + ((f&7)<<2)]);
    }
#pragma unroll
    for (int i = 0; i < BF4; i++) {
        int f = tid + i*T;
        cp16(&sB[(f>>3)*GLD + ((f&7)<<2)], &W[(size_t)(n0 + (f>>3))*K + k0 + ((f&7)<<2)]);
    }
    CP_COMMIT();
}

template<int EPI, int BM, int BN>
__global__ void __launch_bounds__((BM/32)*(BN/((BN>=128)?64:32))*32) k_gemm(
        const float* __restrict__ A, const float* __restrict__ W,
        const float* __restrict__ bias, int g_off,
        float* __restrict__ out, int M, int N, int K) {
    constexpr int WTN = (BN >= 128) ? 64 : 32;
    constexpr int WMC = BM/32, WNC = BN/WTN, NW = WMC*WNC, T = NW*32;
    constexpr int NJ  = WTN/16;
    constexpr int STG = (BM+BN)*GLD;
    constexpr int AF4 = BM*8/T, BF4 = BN*8/T;
    constexpr int CLD = WTN + 4;

    extern __shared__ __align__(16) float smem[];
    const int tid = threadIdx.x, warp = tid >> 5, lane = tid & 31;
    const int wm = warp % WMC, wn = warp / WMC;
    const int m0 = blockIdx.y * BM;
    const int n0 = blockIdx.x * BN;

    wmma::fragment<wmma::accumulator,16,16,8,float> cf[2][NJ];
#pragma unroll
    for (int i = 0; i < 2; i++)
#pragma unroll
        for (int j = 0; j < NJ; j++) wmma::fill_fragment(cf[i][j], 0.0f);

    const int nch = K / GBK;
    g_issue<BM,BN,T,AF4,BF4>(smem,          A, W, m0, n0, K, 0,   tid);
    g_issue<BM,BN,T,AF4,BF4>(smem + STG,    A, W, m0, n0, K, GBK, tid);

    for (int ch = 0; ch < nch; ch++) {
        if (ch == nch-1) { CP_WAIT0(); } else { CP_WAIT1(); }
        __syncthreads();
        float* sA = smem + (ch % 3)*STG;
        float* sB = sA + BM*GLD;
#pragma unroll
        for (int kk = 0; kk < 4; kk++) {
            wmma::fragment<wmma::matrix_a,16,16,8,wmma::precision::tf32,wmma::row_major> af[2];
            wmma::fragment<wmma::matrix_b,16,16,8,wmma::precision::tf32,wmma::col_major> bf[NJ];
#pragma unroll
            for (int i = 0; i < 2; i++) {
                wmma::load_matrix_sync(af[i], sA + (wm*32 + i*16)*GLD + kk*8, GLD);
#pragma unroll
                for (int q = 0; q < af[i].num_elements; q++) af[i].x[q] = wmma::__float_to_tf32(af[i].x[q]);
            }
#pragma unroll
            for (int j = 0; j < NJ; j++) {
                wmma::load_matrix_sync(bf[j], sB + (wn*WTN + j*16)*GLD + kk*8, GLD);
#pragma unroll
                for (int q = 0; q < bf[j].num_elements; q++) bf[j].x[q] = wmma::__float_to_tf32(bf[j].x[q]);
            }
#pragma unroll
            for (int i = 0; i < 2; i++)
#pragma unroll
                for (int j = 0; j < NJ; j++) wmma::mma_sync(cf[i][j], af[i], bf[j], cf[i][j]);
        }
        if (ch + 2 < nch)
            g_issue<BM,BN,T,AF4,BF4>(smem + ((ch+2) % 3)*STG, A, W, m0, n0, K, (ch+2)*GBK, tid);
    }
    __syncthreads();
    // epilogue: stage per-warp 32 x WTN tile in smem
    float* cbuf = smem + warp*(32*CLD);
#pragma unroll
    for (int i = 0; i < 2; i++)
#pragma unroll
        for (int j = 0; j < NJ; j++)
            wmma::store_matrix_sync(cbuf + (i*16)*CLD + j*16, cf[i][j], CLD, wmma::mem_row_major);
    __syncwarp();
    const int nbase = n0 + wn*WTN;
    float bv[WTN/32], gv[WTN/32];
#pragma unroll
    for (int cc = 0; cc < WTN/32; cc++) {
        int ncol = nbase + cc*32 + lane;
        bv[cc] = bias ? bias[ncol] : 0.0f;
        gv[cc] = (EPI == 1) ? g_ada[g_off + ncol] : 0.0f;
    }
#pragma unroll 4
    for (int r = 0; r < 32; r++) {
#pragma unroll
        for (int cc = 0; cc < WTN/32; cc++) {
            float v = cbuf[r*CLD + cc*32 + lane] + bv[cc];
            size_t oi = (size_t)(m0 + wm*32 + r)*N + nbase + cc*32 + lane;
            if (EPI == 0) {
                out[oi] = v;
            } else if (EPI == 1) {
                out[oi] = out[oi] + gv[cc] * v;
            } else {
                float tn = tanhf(0.7978845608028654f*(v + 0.044715f*v*v*v));
                out[oi] = 0.5f*v*(1.0f + tn);
            }
        }
    }
}

// ---------------- fused flash attention: one CTA per (q-tile 64, head), KV tile 64 ----------------
#define FLD  48
#define FLDS 68

__global__ void __launch_bounds__(128) k_flash() {
    extern __shared__ __align__(16) float fs[];
    float* sQ = fs;                 // 64 x 48
    float* sK = fs + 3072;          // 64 x 48
    float* sV = fs + 6144;          // 64 x 48
    float* sO = fs + 9216;          // 64 x 48
    float* sS = fs + 12288;         // 64 x 68 (64 cols used)
    float* sM = fs + 16640;         // 64
    float* sL = fs + 16704;         // 64

    const int tid  = threadIdx.x;   // 128
    const int warp = tid >> 5;
    const int qt = blockIdx.x, hh = blockIdx.y;
    const int l0 = qt*64;
    const float scale = 0.14433756729740643f;   // 48^-0.5
    const int rr = tid >> 1, hf = tid & 1;

    // load scaled Q tile (64 x 48)
#pragma unroll
    for (int i = 0; i < 6; i++) {
        int e = tid + i*128;
        int r = e/12, c4 = e%12;
        float4 v = *(const float4*)&g_qkv[(size_t)(l0+r)*(3*EE) + hh*144 + c4*4];
        v.x *= scale; v.y *= scale; v.z *= scale; v.w *= scale;
        *(float4*)&sQ[r*FLD + c4*4] = v;
    }
    for (int i = tid; i < 64*FLD; i += 128) sO[i] = 0.0f;
    if (tid < 64) { sM[tid] = -1e30f; sL[tid] = 0.0f; }

    // register prefetch of K/V tile 0 (64 rows)
    float4 pk[6], pv[6];
#pragma unroll
    for (int i = 0; i < 6; i++) {
        int e = tid + i*128;
        int r = e/12, c4 = e%12;
        pk[i] = *(const float4*)&g_qkv[(size_t)r*(3*EE) + hh*144 + 48 + c4*4];
        pv[i] = *(const float4*)&g_qkv[(size_t)r*(3*EE) + hh*144 + 96 + c4*4];
    }

    for (int mt = 0; mt < 16; mt++) {
        const int m0 = mt*64;
        __syncthreads();               // protects sK/sV reuse (+ init on iter 0)
#pragma unroll
        for (int i = 0; i < 6; i++) {
            int e = tid + i*128;
            int r = e/12, c4 = e%12;
            *(float4*)&sK[r*FLD + c4*4] = pk[i];
            *(float4*)&sV[r*FLD + c4*4] = pv[i];
        }
        __syncthreads();
        // prefetch next tile (overlaps with S/softmax/PV)
        if (mt < 15) {
            const int mn = m0 + 64;
#pragma unroll
            for (int i = 0; i < 6; i++) {
                int e = tid + i*128;
                int r = e/12, c4 = e%12;
                pk[i] = *(const float4*)&g_qkv[(size_t)(mn+r)*(3*EE) + hh*144 + 48 + c4*4];
                pv[i] = *(const float4*)&g_qkv[(size_t)(mn+r)*(3*EE) + hh*144 + 96 + c4*4];
            }
        }
        // S = Q @ K^T : warp handles rows warp*16..+15, cols 0..63
#pragma unroll
        for (int nt = 0; nt < 4; nt++) {
            wmma::fragment<wmma::accumulator,16,16,8,float> sc;
            wmma::fill_fragment(sc, 0.0f);
#pragma unroll
            for (int k = 0; k < 6; k++) {
                wmma::fragment<wmma::matrix_a,16,16,8,wmma::precision::tf32,wmma::row_major> af;
                wmma::fragment<wmma::matrix_b,16,16,8,wmma::precision::tf32,wmma::col_major> bf;
                wmma::load_matrix_sync(af, sQ + warp*16*FLD + k*8, FLD);
                wmma::load_matrix_sync(bf, sK + nt*16*FLD + k*8, FLD);
#pragma unroll
                for (int q = 0; q < af.num_elements; q++) af.x[q] = wmma::__float_to_tf32(af.x[q]);
#pragma unroll
                for (int q = 0; q < bf.num_elements; q++) bf.x[q] = wmma::__float_to_tf32(bf.x[q]);
                wmma::mma_sync(sc, af, bf, sc);
            }
            wmma::store_matrix_sync(sS + warp*16*FLDS + nt*16, sc, FLDS, wmma::mem_row_major);
        }
        __syncthreads();
        // bias add + online softmax: 2 threads per row, 32 cols each
        {
            const int c0 = hf*32;
            const __nv_bfloat16* bp = &g_bh[((size_t)hh << 20) + ((size_t)(l0+rr) << 10) + m0 + c0];
            float* srow = sS + rr*FLDS + c0;
            float v[32];
            float mloc = -1e30f;
#pragma unroll
            for (int c = 0; c < 32; c++) {
                v[c] = srow[c] + __bfloat162float(bp[c]);
                mloc = fmaxf(mloc, v[c]);
            }
            mloc = fmaxf(mloc, __shfl_xor_sync(0xffffffffu, mloc, 1));
            float mprev = sM[rr];
            float mnew  = fmaxf(mprev, mloc);
            float sum = 0.f;
#pragma unroll
            for (int c = 0; c < 32; c++) {
                float p = __expf(v[c] - mnew);
                srow[c] = p;
                sum += p;
            }
            sum += __shfl_xor_sync(0xffffffffu, sum, 1);
            float factor = __expf(mprev - mnew);
            if (hf == 0) { sM[rr] = mnew; sL[rr] = sL[rr]*factor + sum; }
            float* orow = sO + rr*FLD + hf*24;
#pragma unroll
            for (int c = 0; c < 24; c++) orow[c] *= factor;
        }
        __syncthreads();
        // O += P(64x64) @ V(64x48)
        {
            wmma::fragment<wmma::matrix_a,16,16,8,wmma::precision::tf32,wmma::row_major> pa[8];
#pragma unroll
            for (int kk = 0; kk < 8; kk++) {
                wmma::load_matrix_sync(pa[kk], sS + warp*16*FLDS + kk*8, FLDS);
#pragma unroll
                for (int q = 0; q < pa[kk].num_elements; q++) pa[kk].x[q] = wmma::__float_to_tf32(pa[kk].x[q]);
            }
#pragma unroll
            for (int j = 0; j < 3; j++) {
                wmma::fragment<wmma::accumulator,16,16,8,float> of;
                wmma::load_matrix_sync(of, sO + warp*16*FLD + j*16, FLD, wmma::mem_row_major);
#pragma unroll
                for (int kk = 0; kk < 8; kk++) {
                    wmma::fragment<wmma::matrix_b,16,16,8,wmma::precision::tf32,wmma::row_major> vb;
                    wmma::load_matrix_sync(vb, sV + kk*8*FLD + j*16, FLD);
#pragma unroll
                    for (int q = 0; q < vb.num_elements; q++) vb.x[q] = wmma::__float_to_tf32(vb.x[q]);
                    wmma::mma_sync(of, pa[kk], vb, of);
                }
                wmma::store_matrix_sync(sO + warp*16*FLD + j*16, of, FLD, wmma::mem_row_major);
            }
        }
    }
    __syncthreads();
    // normalize + write y[l, h*48+c]
    {
        float inv = 1.0f / sL[rr];
        const float* orow = sO + rr*FLD + hf*24;
        float* dst = g_y + (size_t)(l0+rr)*EE + hh*HDIM + hf*24;
#pragma unroll
        for (int c = 0; c < 24; c++) dst[c] = orow[c]*inv;
    }
}

// ---------------- driver ----------------
static const int SM_BIG   = 3*(128+128)*GLD*4;   // 110592 B (3-stage 128x128)
static const int SM_SMALL = 3*(64+64)*GLD*4;     //  55296 B (3-stage 64x64)
static const int SM_FLASH = 16768*4;             //  67072 B

extern "C" void kernel_launch(void* const* d_in, const int* in_sizes, int n_in,
                              void* d_out, int out_size) {
    const float* z    = (const float*)d_in[0];
    const float* t    = (const float*)d_in[1];
    const float* bias = (const float*)d_in[2];
    const float* ln_g = (const float*)d_in[3];
    const float* ln_b = (const float*)d_in[4];
    const float* p2sw = (const float*)d_in[5];
    const float* t0w  = (const float*)d_in[6];
    const float* t0b  = (const float*)d_in[7];
    const float* t2w  = (const float*)d_in[8];
    const float* t2b  = (const float*)d_in[9];
    const float* pw   = (const float*)d_in[10];
    const float* ow   = (const float*)d_in[11];
    const float* ob   = (const float*)d_in[12];
    const float* aw   = (const float*)d_in[13];
    const float* ab   = (const float*)d_in[14];
    const float* f1w  = (const float*)d_in[15];
    const float* f1b  = (const float*)d_in[16];
    const float* f2w  = (const float*)d_in[17];
    const float* f2b  = (const float*)d_in[18];
    const float* faw  = (const float*)d_in[19];
    const float* fab  = (const float*)d_in[20];
    const float* fw   = (const float*)d_in[21];
    const float* fb   = (const float*)d_in[22];

    float *px, *ph, *pq, *py, *pm;
    cudaGetSymbolAddress((void**)&px, g_x);
    cudaGetSymbolAddress((void**)&ph, g_h);
    cudaGetSymbolAddress((void**)&pq, g_qkv);
    cudaGetSymbolAddress((void**)&py, g_y);
    cudaGetSymbolAddress((void**)&pm, g_mlp);

    cudaFuncSetAttribute(k_gemm<0,128,128>, cudaFuncAttributeMaxDynamicSharedMemorySize, SM_BIG);
    cudaFuncSetAttribute(k_gemm<2,128,128>, cudaFuncAttributeMaxDynamicSharedMemorySize, SM_BIG);
    cudaFuncSetAttribute(k_gemm<0,64,64>,   cudaFuncAttributeMaxDynamicSharedMemorySize, SM_SMALL);
    cudaFuncSetAttribute(k_gemm<1,64,64>,   cudaFuncAttributeMaxDynamicSharedMemorySize, SM_SMALL);
    cudaFuncSetAttribute(k_flash,           cudaFuncAttributeMaxDynamicSharedMemorySize, SM_FLASH);

    k_copy<<<768, 1024>>>(z);
    k_prep<<<1, 128>>>(ln_g, ln_b, p2sw);
    k_bias<<<4096, 256>>>(bias);
    k_time1<<<96, 256>>>(t, t0w, t0b);
    k_time2<<<96, 256>>>(t2w, t2b);
    k_ada<<<4800, 256>>>(aw, ab, faw, fab);

    for (int d = 0; d < NDEPTH; d++) {
        const int base = d*6*EE;
        // attention branch
        k_lnmod<<<1024, 256>>>(px, base, base + EE, ph);
        k_gemm<0,128,128><<<dim3(18, 8), 256, SM_BIG>>>(ph, pw + (size_t)d*3*EE*EE, nullptr, 0,
                                                        pq, LL, 3*EE, EE);
        k_flash<<<dim3(16, 16), 128, SM_FLASH>>>();
        k_gemm<1,64,64><<<dim3(12, 16), 128, SM_SMALL>>>(py, ow + (size_t)d*EE*EE, ob + d*EE, base + 2*EE,
                                                         px, LL, EE, EE);
        // MLP branch
        k_lnmod<<<1024, 256>>>(px, base + 3*EE, base + 4*EE, ph);
        k_gemm<2,128,128><<<dim3(24, 8), 256, SM_BIG>>>(ph, f1w + (size_t)d*MLPD*EE, f1b + d*MLPD, 0,
                                                        pm, LL, MLPD, EE);
        k_gemm<1,64,64><<<dim3(12, 16), 128, SM_SMALL>>>(pm, f2w + (size_t)d*EE*MLPD, f2b + d*EE, base + 5*EE,
                                                         px, LL, EE, MLPD);
    }
    // final
    const int foff = NDEPTH*6*EE;
    k_lnmod<<<1024, 256>>>(px, foff, foff + EE, ph);
    k_gemm<0,64,64><<<dim3(12, 16), 128, SM_SMALL>>>(ph, fw, fb, 0, (float*)d_out, LL, EE, EE);
}

// round 13
// speedup vs baseline: 1.0413x; 1.0376x over previous
#include <cuda_runtime.h>
#include <cuda_bf16.h>
#include <mma.h>
#include <cmath>

using namespace nvcuda;

#define LL     1024
#define EE     768
#define PPD    128
#define HH     16
#define HDIM   48
#define NDEPTH 8
#define MLPD   3072
#define NFREQ  256

// ---------------- device-global scratch (no allocations allowed) ----------------
__device__ __align__(16) float g_x[LL*EE];
__device__ __align__(16) float g_h[LL*EE];
__device__ __align__(16) float g_qkv[LL*3*EE];
__device__ __align__(16) float g_y[LL*EE];
__device__ __align__(16) float g_mlp[LL*MLPD];
__device__ __align__(16) __nv_bfloat16 g_bh[(size_t)HH*LL*LL];   // 32 MB, [h][l][m]
__device__ float g_cpre[EE];
__device__ float g_cs[EE];
__device__ float g_ada[NDEPTH*6*EE + 2*EE];
__device__ float g_Apw[HH*PPD];
__device__ float g_Spw[HH];
__device__ float g_Cpw[HH];

__device__ __forceinline__ void cp16(float* s, const float* g) {
    unsigned sa = (unsigned)__cvta_generic_to_shared(s);
    asm volatile("cp.async.cg.shared.global [%0], [%1], 16;\n" :: "r"(sa), "l"(g));
}
#define CP_COMMIT() asm volatile("cp.async.commit_group;\n" ::: "memory")
#define CP_WAIT0()  asm volatile("cp.async.wait_group 0;\n" ::: "memory")
#define CP_WAIT1()  asm volatile("cp.async.wait_group 1;\n" ::: "memory")

// ---------------- init ----------------
__global__ void k_copy(const float* __restrict__ z) {
    int i = blockIdx.x*1024 + threadIdx.x;
    g_x[i] = z[i];
}

__global__ void k_prep(const float* __restrict__ g, const float* __restrict__ beta,
                       const float* __restrict__ w) {
    const int p = threadIdx.x; // 128
    for (int h = 0; h < HH; h++)
        g_Apw[h*PPD + p] = g[p] * w[h*PPD + p];
    if (p < HH) {
        float s = 0.f, c = 0.f;
        for (int q = 0; q < PPD; q++) {
            s += g[q]    * w[p*PPD + q];
            c += beta[q] * w[p*PPD + q];
        }
        g_Spw[p] = s; g_Cpw[p] = c;
    }
}

// ---------------- bias LN + head projection: 512 MB read, one thread per row ----------------
__global__ void __launch_bounds__(256) k_bias(const float* __restrict__ bias) {
    __shared__ __align__(16) float sA[HH*PPD];
    __shared__ float sSh[HH], sCh[HH];
    const int tid = threadIdx.x;
    for (int i = tid; i < HH*PPD; i += 256) sA[i] = g_Apw[i];
    if (tid < HH) { sSh[tid] = g_Spw[tid]; sCh[tid] = g_Cpw[tid]; }
    __syncthreads();
    const int row = blockIdx.x*256 + tid;      // row = l*1024 + m
    const float* xr = bias + (size_t)row*PPD;
    float acc[HH];
#pragma unroll
    for (int h = 0; h < HH; h++) acc[h] = 0.f;
    float s = 0.f, ss = 0.f;
#pragma unroll
    for (int ch = 0; ch < 4; ch++) {
        float4 xv[8];
#pragma unroll
        for (int j = 0; j < 8; j++) xv[j] = *(const float4*)&xr[ch*32 + j*4];
#pragma unroll
        for (int j = 0; j < 8; j++) {
            s  += xv[j].x + xv[j].y + xv[j].z + xv[j].w;
            ss += xv[j].x*xv[j].x + xv[j].y*xv[j].y + xv[j].z*xv[j].z + xv[j].w*xv[j].w;
        }
#pragma unroll
        for (int h = 0; h < HH; h++) {
            const float* ar = &sA[h*PPD + ch*32];
            float a0 = 0.f;
#pragma unroll
            for (int j = 0; j < 8; j++) {
                float4 av = *(const float4*)&ar[j*4];
                a0 += xv[j].x*av.x + xv[j].y*av.y + xv[j].z*av.z + xv[j].w*av.w;
            }
            acc[h] += a0;
        }
    }
    const float mu   = s * (1.0f/PPD);
    const float rstd = rsqrtf(ss*(1.0f/PPD) - mu*mu + 1e-6f);
    const int l = row >> 10, m = row & 1023;
#pragma unroll
    for (int h = 0; h < HH; h++) {
        float v = rstd*(acc[h] - mu*sSh[h]) + sCh[h];
        g_bh[((size_t)h << 20) + ((size_t)l << 10) + m] = __float2bfloat16(v);
    }
}

// ---------------- time embedding chain ----------------
__global__ void __launch_bounds__(256) k_time1(const float* __restrict__ t,
                                               const float* __restrict__ t0_w,
                                               const float* __restrict__ t0_b) {
    __shared__ float emb[NFREQ];
    const int tid = threadIdx.x;  // 256
    {
        int i = tid & 127;
        float f   = expf(-9.210340371976184f * (float)i / 128.0f);
        float arg = t[0] * f;
        emb[tid] = (tid < 128) ? cosf(arg) : sinf(arg);
    }
    __syncthreads();
    const int warp = tid >> 5, lane = tid & 31;
    const int j = blockIdx.x*8 + warp;
    const float* w = t0_w + (size_t)j*NFREQ;
    float acc = 0.f;
#pragma unroll
    for (int i = 0; i < 8; i++) acc += emb[lane + i*32] * w[lane + i*32];
#pragma unroll
    for (int o = 16; o > 0; o >>= 1) acc += __shfl_xor_sync(0xffffffffu, acc, o);
    if (lane == 0) {
        float a = acc + t0_b[j];
        g_cpre[j] = a / (1.f + expf(-a));
    }
}

__global__ void __launch_bounds__(256) k_time2(const float* __restrict__ t2_w,
                                               const float* __restrict__ t2_b) {
    __shared__ float cp[EE];
    const int tid = threadIdx.x;
    for (int i = tid; i < EE; i += 256) cp[i] = g_cpre[i];
    __syncthreads();
    const int warp = tid >> 5, lane = tid & 31;
    const int j = blockIdx.x*8 + warp;
    const float* w = t2_w + (size_t)j*EE;
    float acc = 0.f;
#pragma unroll
    for (int i = 0; i < 24; i++) acc += cp[lane + i*32] * w[lane + i*32];
#pragma unroll
    for (int o = 16; o > 0; o >>= 1) acc += __shfl_xor_sync(0xffffffffu, acc, o);
    if (lane == 0) {
        float a = acc + t2_b[j];
        g_cs[j] = a / (1.f + expf(-a));
    }
}

// all adaLN vectors, one warp per row
__global__ void k_ada(const float* __restrict__ aw, const float* __restrict__ ab,
                      const float* __restrict__ fw, const float* __restrict__ fb) {
    const int gw   = (blockIdx.x*blockDim.x + threadIdx.x) >> 5;
    const int lane = threadIdx.x & 31;
    const int total = NDEPTH*6*EE + 2*EE;
    if (gw >= total) return;
    const float* wrow; float b;
    if (gw < NDEPTH*6*EE) { wrow = aw + (size_t)gw*EE; b = ab[gw]; }
    else { int r = gw - NDEPTH*6*EE; wrow = fw + (size_t)r*EE; b = fb[r]; }
    float acc = 0.f;
    for (int i = lane; i < EE; i += 32) acc += g_cs[i]*wrow[i];
#pragma unroll
    for (int o = 16; o > 0; o >>= 1) acc += __shfl_xor_sync(0xffffffffu, acc, o);
    if (lane == 0) g_ada[gw] = acc + b;
}

// ---------------- LayerNorm + adaLN modulation ----------------
__global__ void __launch_bounds__(256) k_lnmod(const float* __restrict__ x,
                                               int sh_off, int sc_off,
                                               float* __restrict__ out) {
    const int row = blockIdx.x, tid = threadIdx.x;
    const float* xr = x + (size_t)row*EE;
    float v0 = xr[tid], v1 = xr[tid+256], v2 = xr[tid+512];
    float s  = v0 + v1 + v2;
    float ss = v0*v0 + v1*v1 + v2*v2;
    __shared__ float rs[8], rss[8];
#pragma unroll
    for (int o = 16; o > 0; o >>= 1) {
        s  += __shfl_xor_sync(0xffffffffu, s,  o);
        ss += __shfl_xor_sync(0xffffffffu, ss, o);
    }
    if ((tid & 31) == 0) { rs[tid>>5] = s; rss[tid>>5] = ss; }
    __syncthreads();
    float st = 0.f, sst = 0.f;
#pragma unroll
    for (int i = 0; i < 8; i++) { st += rs[i]; sst += rss[i]; }
    const float mu   = st * (1.0f/EE);
    const float rstd = rsqrtf(sst*(1.0f/EE) - mu*mu + 1e-6f);
    const float* sh = g_ada + sh_off;
    const float* sc = g_ada + sc_off;
    float* orow = out + (size_t)row*EE;
    orow[tid]     = (v0-mu)*rstd*(1.f+sc[tid])     + sh[tid];
    orow[tid+256] = (v1-mu)*rstd*(1.f+sc[tid+256]) + sh[tid+256];
    orow[tid+512] = (v2-mu)*rstd*(1.f+sc[tid+512]) + sh[tid+512];
}

// ---------------- tf32 wmma GEMM, cp.async 3-stage pipeline, 256 threads ----------------
// C(MxN) = A(MxK) @ W(NxK)^T.  BN = 64 fixed, 8 warps, warp tile WTM x 32.
// EPI 0: out = acc+bias    EPI 1: out += g_ada[g_off+n]*(acc+bias)    EPI 2: out = gelu_tanh(acc+bias)
#define GBK 32
#define GLD 36

template<int BM, int AF4, int BF4>
__device__ __forceinline__ void g_issue(float* stage, const float* A, const float* W,
                                        int m0, int n0, int K, int k0, int tid) {
    float* sA = stage;
    float* sB = stage + BM*GLD;
#pragma unroll
    for (int i = 0; i < AF4; i++) {
        int f = tid + i*256;
        cp16(&sA[(f>>3)*GLD + ((f&7)<<2)], &A[(size_t)(m0 + (f>>3))*K + k0 + ((f&7)<<2)]);
    }
#pragma unroll
    for (int i = 0; i < BF4; i++) {
        int f = tid + i*256;
        cp16(&sB[(f>>3)*GLD + ((f&7)<<2)], &W[(size_t)(n0 + (f>>3))*K + k0 + ((f&7)<<2)]);
    }
    CP_COMMIT();
}

template<int EPI, int BM, int WTM>
__global__ void __launch_bounds__(256) k_gemm(
        const float* __restrict__ A, const float* __restrict__ W,
        const float* __restrict__ bias, int g_off,
        float* __restrict__ out, int M, int N, int K) {
    constexpr int BN  = 64;
    constexpr int WMC = BM/WTM;               // warps along M (4)
    constexpr int MI  = WTM/16;
    constexpr int NJ  = 2;                    // 32 cols per warp
    constexpr int STG = (BM+BN)*GLD;
    constexpr int AF4 = BM*8/256, BF4 = BN*8/256;
    constexpr int CLD = 36;

    extern __shared__ __align__(16) float smem[];
    const int tid = threadIdx.x, warp = tid >> 5, lane = tid & 31;
    const int wm = warp % WMC, wn = warp / WMC;
    const int m0 = blockIdx.y * BM;
    const int n0 = blockIdx.x * BN;

    wmma::fragment<wmma::accumulator,16,16,8,float> cf[MI][NJ];
#pragma unroll
    for (int i = 0; i < MI; i++)
#pragma unroll
        for (int j = 0; j < NJ; j++) wmma::fill_fragment(cf[i][j], 0.0f);

    const int nch = K / GBK;
    g_issue<BM,AF4,BF4>(smem,       A, W, m0, n0, K, 0,   tid);
    g_issue<BM,AF4,BF4>(smem + STG, A, W, m0, n0, K, GBK, tid);

    for (int ch = 0; ch < nch; ch++) {
        if (ch == nch-1) { CP_WAIT0(); } else { CP_WAIT1(); }
        __syncthreads();
        float* sA = smem + (ch % 3)*STG;
        float* sB = sA + BM*GLD;
#pragma unroll
        for (int kk = 0; kk < 4; kk++) {
            wmma::fragment<wmma::matrix_a,16,16,8,wmma::precision::tf32,wmma::row_major> af[MI];
            wmma::fragment<wmma::matrix_b,16,16,8,wmma::precision::tf32,wmma::col_major> bf[NJ];
#pragma unroll
            for (int i = 0; i < MI; i++) {
                wmma::load_matrix_sync(af[i], sA + (wm*WTM + i*16)*GLD + kk*8, GLD);
#pragma unroll
                for (int q = 0; q < af[i].num_elements; q++) af[i].x[q] = wmma::__float_to_tf32(af[i].x[q]);
            }
#pragma unroll
            for (int j = 0; j < NJ; j++) {
                wmma::load_matrix_sync(bf[j], sB + (wn*32 + j*16)*GLD + kk*8, GLD);
#pragma unroll
                for (int q = 0; q < bf[j].num_elements; q++) bf[j].x[q] = wmma::__float_to_tf32(bf[j].x[q]);
            }
#pragma unroll
            for (int i = 0; i < MI; i++)
#pragma unroll
                for (int j = 0; j < NJ; j++) wmma::mma_sync(cf[i][j], af[i], bf[j], cf[i][j]);
        }
        if (ch + 2 < nch)
            g_issue<BM,AF4,BF4>(smem + ((ch+2) % 3)*STG, A, W, m0, n0, K, (ch+2)*GBK, tid);
    }
    __syncthreads();
    // epilogue: stage per-warp WTM x 32 tile in smem
    float* cbuf = smem + warp*(WTM*CLD);
#pragma unroll
    for (int i = 0; i < MI; i++)
#pragma unroll
        for (int j = 0; j < NJ; j++)
            wmma::store_matrix_sync(cbuf + (i*16)*CLD + j*16, cf[i][j], CLD, wmma::mem_row_major);
    __syncwarp();
    const int ncol = n0 + wn*32 + lane;
    const float bv = bias ? bias[ncol] : 0.0f;
    const float gv = (EPI == 1) ? g_ada[g_off + ncol] : 0.0f;
#pragma unroll
    for (int r = 0; r < WTM; r++) {
        float v = cbuf[r*CLD + lane] + bv;
        size_t oi = (size_t)(m0 + wm*WTM + r)*N + ncol;
        if (EPI == 0) {
            out[oi] = v;
        } else if (EPI == 1) {
            out[oi] = out[oi] + gv * v;
        } else {
            float tn = tanhf(0.7978845608028654f*(v + 0.044715f*v*v*v));
            out[oi] = 0.5f*v*(1.0f + tn);
        }
    }
}

// ---------------- fused flash attention: one CTA per (q-tile 64, head), KV tile 64 ----------------
#define FLD  48
#define FLDS 68

__global__ void __launch_bounds__(128) k_flash() {
    extern __shared__ __align__(16) float fs[];
    float* sQ = fs;                 // 64 x 48
    float* sK = fs + 3072;          // 64 x 48
    float* sV = fs + 6144;          // 64 x 48
    float* sO = fs + 9216;          // 64 x 48
    float* sS = fs + 12288;         // 64 x 68 (64 cols used)
    float* sM = fs + 16640;         // 64
    float* sL = fs + 16704;         // 64

    const int tid  = threadIdx.x;   // 128
    const int warp = tid >> 5;
    const int qt = blockIdx.x, hh = blockIdx.y;
    const int l0 = qt*64;
    const float scale = 0.14433756729740643f;   // 48^-0.5
    const int rr = tid >> 1, hf = tid & 1;

    // load scaled Q tile (64 x 48)
#pragma unroll
    for (int i = 0; i < 6; i++) {
        int e = tid + i*128;
        int r = e/12, c4 = e%12;
        float4 v = *(const float4*)&g_qkv[(size_t)(l0+r)*(3*EE) + hh*144 + c4*4];
        v.x *= scale; v.y *= scale; v.z *= scale; v.w *= scale;
        *(float4*)&sQ[r*FLD + c4*4] = v;
    }
    for (int i = tid; i < 64*FLD; i += 128) sO[i] = 0.0f;
    if (tid < 64) { sM[tid] = -1e30f; sL[tid] = 0.0f; }

    // register prefetch of K/V tile 0 (64 rows)
    float4 pk[6], pv[6];
#pragma unroll
    for (int i = 0; i < 6; i++) {
        int e = tid + i*128;
        int r = e/12, c4 = e%12;
        pk[i] = *(const float4*)&g_qkv[(size_t)r*(3*EE) + hh*144 + 48 + c4*4];
        pv[i] = *(const float4*)&g_qkv[(size_t)r*(3*EE) + hh*144 + 96 + c4*4];
    }

    for (int mt = 0; mt < 16; mt++) {
        const int m0 = mt*64;
        __syncthreads();               // protects sK/sV reuse (+ init on iter 0)
#pragma unroll
        for (int i = 0; i < 6; i++) {
            int e = tid + i*128;
            int r = e/12, c4 = e%12;
            *(float4*)&sK[r*FLD + c4*4] = pk[i];
            *(float4*)&sV[r*FLD + c4*4] = pv[i];
        }
        __syncthreads();
        // prefetch next tile (overlaps with S/softmax/PV)
        if (mt < 15) {
            const int mn = m0 + 64;
#pragma unroll
            for (int i = 0; i < 6; i++) {
                int e = tid + i*128;
                int r = e/12, c4 = e%12;
                pk[i] = *(const float4*)&g_qkv[(size_t)(mn+r)*(3*EE) + hh*144 + 48 + c4*4];
                pv[i] = *(const float4*)&g_qkv[(size_t)(mn+r)*(3*EE) + hh*144 + 96 + c4*4];
            }
        }
        // S = Q @ K^T : warp handles rows warp*16..+15, cols 0..63
#pragma unroll
        for (int nt = 0; nt < 4; nt++) {
            wmma::fragment<wmma::accumulator,16,16,8,float> sc;
            wmma::fill_fragment(sc, 0.0f);
#pragma unroll
            for (int k = 0; k < 6; k++) {
                wmma::fragment<wmma::matrix_a,16,16,8,wmma::precision::tf32,wmma::row_major> af;
                wmma::fragment<wmma::matrix_b,16,16,8,wmma::precision::tf32,wmma::col_major> bf;
                wmma::load_matrix_sync(af, sQ + warp*16*FLD + k*8, FLD);
                wmma::load_matrix_sync(bf, sK + nt*16*FLD + k*8, FLD);
#pragma unroll
                for (int q = 0; q < af.num_elements; q++) af.x[q] = wmma::__float_to_tf32(af.x[q]);
#pragma unroll
                for (int q = 0; q < bf.num_elements; q++) bf.x[q] = wmma::__float_to_tf32(bf.x[q]);
                wmma::mma_sync(sc, af, bf, sc);
            }
            wmma::store_matrix_sync(sS + warp*16*FLDS + nt*16, sc, FLDS, wmma::mem_row_major);
        }
        __syncthreads();
        // bias add + online softmax: 2 threads per row, 32 cols each
        {
            const int c0 = hf*32;
            const __nv_bfloat16* bp = &g_bh[((size_t)hh << 20) + ((size_t)(l0+rr) << 10) + m0 + c0];
            float* srow = sS + rr*FLDS + c0;
            float v[32];
            float mloc = -1e30f;
#pragma unroll
            for (int c = 0; c < 32; c++) {
                v[c] = srow[c] + __bfloat162float(bp[c]);
                mloc = fmaxf(mloc, v[c]);
            }
            mloc = fmaxf(mloc, __shfl_xor_sync(0xffffffffu, mloc, 1));
            float mprev = sM[rr];
            float mnew  = fmaxf(mprev, mloc);
            float sum = 0.f;
#pragma unroll
            for (int c = 0; c < 32; c++) {
                float p = __expf(v[c] - mnew);
                srow[c] = p;
                sum += p;
            }
            sum += __shfl_xor_sync(0xffffffffu, sum, 1);
            float factor = __expf(mprev - mnew);
            if (hf == 0) { sM[rr] = mnew; sL[rr] = sL[rr]*factor + sum; }
            float* orow = sO + rr*FLD + hf*24;
#pragma unroll
            for (int c = 0; c < 24; c++) orow[c] *= factor;
        }
        __syncthreads();
        // O += P(64x64) @ V(64x48)
        {
            wmma::fragment<wmma::matrix_a,16,16,8,wmma::precision::tf32,wmma::row_major> pa[8];
#pragma unroll
            for (int kk = 0; kk < 8; kk++) {
                wmma::load_matrix_sync(pa[kk], sS + warp*16*FLDS + kk*8, FLDS);
#pragma unroll
                for (int q = 0; q < pa[kk].num_elements; q++) pa[kk].x[q] = wmma::__float_to_tf32(pa[kk].x[q]);
            }
#pragma unroll
            for (int j = 0; j < 3; j++) {
                wmma::fragment<wmma::accumulator,16,16,8,float> of;
                wmma::load_matrix_sync(of, sO + warp*16*FLD + j*16, FLD, wmma::mem_row_major);
#pragma unroll
                for (int kk = 0; kk < 8; kk++) {
                    wmma::fragment<wmma::matrix_b,16,16,8,wmma::precision::tf32,wmma::row_major> vb;
                    wmma::load_matrix_sync(vb, sV + kk*8*FLD + j*16, FLD);
#pragma unroll
                    for (int q = 0; q < vb.num_elements; q++) vb.x[q] = wmma::__float_to_tf32(vb.x[q]);
                    wmma::mma_sync(of, pa[kk], vb, of);
                }
                wmma::store_matrix_sync(sO + warp*16*FLD + j*16, of, FLD, wmma::mem_row_major);
            }
        }
    }
    __syncthreads();
    // normalize + write y[l, h*48+c]
    {
        float inv = 1.0f / sL[rr];
        const float* orow = sO + rr*FLD + hf*24;
        float* dst = g_y + (size_t)(l0+rr)*EE + hh*HDIM + hf*24;
#pragma unroll
        for (int c = 0; c < 24; c++) dst[c] = orow[c]*inv;
    }
}

// ---------------- driver ----------------
static const int SM_BIG   = 3*(128+64)*GLD*4;   // 82944 B  (3-stage 128x64) -> 2 CTA/SM
static const int SM_SMALL = 3*(64+64)*GLD*4;    // 55296 B  (3-stage 64x64)  -> 4 CTA/SM
static const int SM_FLASH = 16768*4;            // 67072 B

extern "C" void kernel_launch(void* const* d_in, const int* in_sizes, int n_in,
                              void* d_out, int out_size) {
    const float* z    = (const float*)d_in[0];
    const float* t    = (const float*)d_in[1];
    const float* bias = (const float*)d_in[2];
    const float* ln_g = (const float*)d_in[3];
    const float* ln_b = (const float*)d_in[4];
    const float* p2sw = (const float*)d_in[5];
    const float* t0w  = (const float*)d_in[6];
    const float* t0b  = (const float*)d_in[7];
    const float* t2w  = (const float*)d_in[8];
    const float* t2b  = (const float*)d_in[9];
    const float* pw   = (const float*)d_in[10];
    const float* ow   = (const float*)d_in[11];
    const float* ob   = (const float*)d_in[12];
    const float* aw   = (const float*)d_in[13];
    const float* ab   = (const float*)d_in[14];
    const float* f1w  = (const float*)d_in[15];
    const float* f1b  = (const float*)d_in[16];
    const float* f2w  = (const float*)d_in[17];
    const float* f2b  = (const float*)d_in[18];
    const float* faw  = (const float*)d_in[19];
    const float* fab  = (const float*)d_in[20];
    const float* fw   = (const float*)d_in[21];
    const float* fb   = (const float*)d_in[22];

    float *px, *ph, *pq, *py, *pm;
    cudaGetSymbolAddress((void**)&px, g_x);
    cudaGetSymbolAddress((void**)&ph, g_h);
    cudaGetSymbolAddress((void**)&pq, g_qkv);
    cudaGetSymbolAddress((void**)&py, g_y);
    cudaGetSymbolAddress((void**)&pm, g_mlp);

    cudaFuncSetAttribute(k_gemm<0,128,32>, cudaFuncAttributeMaxDynamicSharedMemorySize, SM_BIG);
    cudaFuncSetAttribute(k_gemm<2,128,32>, cudaFuncAttributeMaxDynamicSharedMemorySize, SM_BIG);
    cudaFuncSetAttribute(k_gemm<0,64,16>,  cudaFuncAttributeMaxDynamicSharedMemorySize, SM_SMALL);
    cudaFuncSetAttribute(k_gemm<1,64,16>,  cudaFuncAttributeMaxDynamicSharedMemorySize, SM_SMALL);
    cudaFuncSetAttribute(k_flash,          cudaFuncAttributeMaxDynamicSharedMemorySize, SM_FLASH);

    // ---- launch order chosen so launch #6 (ncu -s 5 -c 1) is the block-0 qkv GEMM ----
    k_prep<<<1, 128>>>(ln_g, ln_b, p2sw);                       // 1
    k_time1<<<96, 256>>>(t, t0w, t0b);                          // 2
    k_time2<<<96, 256>>>(t2w, t2b);                             // 3
    k_ada<<<4800, 256>>>(aw, ab, faw, fab);                     // 4
    k_lnmod<<<1024, 256>>>(z, 0, EE, ph);                       // 5 (block-0 LN reads z directly)
    k_gemm<0,128,32><<<dim3(36, 8), 256, SM_BIG>>>(             // 6  <-- profiled next round
        ph, pw, nullptr, 0, pq, LL, 3*EE, EE);
    k_bias<<<4096, 256>>>(bias);                                // 7
    k_copy<<<768, 1024>>>(z);                                   // 8
    k_flash<<<dim3(16, 16), 128, SM_FLASH>>>();                 // 9
    k_gemm<1,64,16><<<dim3(12, 16), 256, SM_SMALL>>>(py, ow, ob, 2*EE, px, LL, EE, EE);
    k_lnmod<<<1024, 256>>>(px, 3*EE, 4*EE, ph);
    k_gemm<2,128,32><<<dim3(48, 8), 256, SM_BIG>>>(ph, f1w, f1b, 0, pm, LL, MLPD, EE);
    k_gemm<1,64,16><<<dim3(12, 16), 256, SM_SMALL>>>(pm, f2w, f2b, 5*EE, px, LL, EE, MLPD);

    for (int d = 1; d < NDEPTH; d++) {
        const int base = d*6*EE;
        // attention branch
        k_lnmod<<<1024, 256>>>(px, base, base + EE, ph);
        k_gemm<0,128,32><<<dim3(36, 8), 256, SM_BIG>>>(ph, pw + (size_t)d*3*EE*EE, nullptr, 0,
                                                       pq, LL, 3*EE, EE);
        k_flash<<<dim3(16, 16), 128, SM_FLASH>>>();
        k_gemm<1,64,16><<<dim3(12, 16), 256, SM_SMALL>>>(py, ow + (size_t)d*EE*EE, ob + d*EE, base + 2*EE,
                                                         px, LL, EE, EE);
        // MLP branch
        k_lnmod<<<1024, 256>>>(px, base + 3*EE, base + 4*EE, ph);
        k_gemm<2,128,32><<<dim3(48, 8), 256, SM_BIG>>>(ph, f1w + (size_t)d*MLPD*EE, f1b + d*MLPD, 0,
                                                       pm, LL, MLPD, EE);
        k_gemm<1,64,16><<<dim3(12, 16), 256, SM_SMALL>>>(pm, f2w + (size_t)d*EE*MLPD, f2b + d*EE, base + 5*EE,
                                                         px, LL, EE, MLPD);
    }
    // final
    const int foff = NDEPTH*6*EE;
    k_lnmod<<<1024, 256>>>(px, foff, foff + EE, ph);
    k_gemm<0,64,16><<<dim3(12, 16), 256, SM_SMALL>>>(ph, fw, fb, 0, (float*)d_out, LL, EE, EE);
}

// round 14
// speedup vs baseline: 1.0452x; 1.0038x over previous
#include <cuda_runtime.h>
#include <cuda_bf16.h>
#include <mma.h>
#include <cmath>

using namespace nvcuda;

#define LL     1024
#define EE     768
#define PPD    128
#define HH     16
#define HDIM   48
#define NDEPTH 8
#define MLPD   3072
#define NFREQ  256

// ---------------- device-global scratch (no allocations allowed) ----------------
__device__ __align__(16) float g_x[LL*EE];
__device__ __align__(16) float g_h[LL*EE];
__device__ __align__(16) float g_qkv[LL*3*EE];
__device__ __align__(16) float g_y[LL*EE];
__device__ __align__(16) float g_mlp[LL*MLPD];
__device__ __align__(16) __nv_bfloat16 g_bh[(size_t)HH*LL*LL];   // 32 MB, [h][l][m]
__device__ float g_cpre[EE];
__device__ float g_cs[EE];
__device__ float g_ada[NDEPTH*6*EE + 2*EE];
__device__ float g_Apw[HH*PPD];
__device__ float g_Spw[HH];
__device__ float g_Cpw[HH];

__device__ __forceinline__ void cp16(float* s, const float* g) {
    unsigned sa = (unsigned)__cvta_generic_to_shared(s);
    asm volatile("cp.async.cg.shared.global [%0], [%1], 16;\n" :: "r"(sa), "l"(g));
}
#define CP_COMMIT() asm volatile("cp.async.commit_group;\n" ::: "memory")
#define CP_WAIT0()  asm volatile("cp.async.wait_group 0;\n" ::: "memory")
#define CP_WAIT1()  asm volatile("cp.async.wait_group 1;\n" ::: "memory")

// ---------------- init ----------------
__global__ void k_copy(const float* __restrict__ z) {
    int i = blockIdx.x*1024 + threadIdx.x;
    g_x[i] = z[i];
}

__global__ void k_prep(const float* __restrict__ g, const float* __restrict__ beta,
                       const float* __restrict__ w) {
    const int p = threadIdx.x; // 128
    for (int h = 0; h < HH; h++)
        g_Apw[h*PPD + p] = g[p] * w[h*PPD + p];
    if (p < HH) {
        float s = 0.f, c = 0.f;
        for (int q = 0; q < PPD; q++) {
            s += g[q]    * w[p*PPD + q];
            c += beta[q] * w[p*PPD + q];
        }
        g_Spw[p] = s; g_Cpw[p] = c;
    }
}

// ---------------- bias LN + head projection: 512 MB read, one thread per row ----------------
__global__ void __launch_bounds__(256) k_bias(const float* __restrict__ bias) {
    __shared__ __align__(16) float sA[HH*PPD];
    __shared__ float sSh[HH], sCh[HH];
    const int tid = threadIdx.x;
    for (int i = tid; i < HH*PPD; i += 256) sA[i] = g_Apw[i];
    if (tid < HH) { sSh[tid] = g_Spw[tid]; sCh[tid] = g_Cpw[tid]; }
    __syncthreads();
    const int row = blockIdx.x*256 + tid;      // row = l*1024 + m
    const float* xr = bias + (size_t)row*PPD;
    float acc[HH];
#pragma unroll
    for (int h = 0; h < HH; h++) acc[h] = 0.f;
    float s = 0.f, ss = 0.f;
#pragma unroll
    for (int ch = 0; ch < 4; ch++) {
        float4 xv[8];
#pragma unroll
        for (int j = 0; j < 8; j++) xv[j] = *(const float4*)&xr[ch*32 + j*4];
#pragma unroll
        for (int j = 0; j < 8; j++) {
            s  += xv[j].x + xv[j].y + xv[j].z + xv[j].w;
            ss += xv[j].x*xv[j].x + xv[j].y*xv[j].y + xv[j].z*xv[j].z + xv[j].w*xv[j].w;
        }
#pragma unroll
        for (int h = 0; h < HH; h++) {
            const float* ar = &sA[h*PPD + ch*32];
            float a0 = 0.f;
#pragma unroll
            for (int j = 0; j < 8; j++) {
                float4 av = *(const float4*)&ar[j*4];
                a0 += xv[j].x*av.x + xv[j].y*av.y + xv[j].z*av.z + xv[j].w*av.w;
            }
            acc[h] += a0;
        }
    }
    const float mu   = s * (1.0f/PPD);
    const float rstd = rsqrtf(ss*(1.0f/PPD) - mu*mu + 1e-6f);
    const int l = row >> 10, m = row & 1023;
#pragma unroll
    for (int h = 0; h < HH; h++) {
        float v = rstd*(acc[h] - mu*sSh[h]) + sCh[h];
        g_bh[((size_t)h << 20) + ((size_t)l << 10) + m] = __float2bfloat16(v);
    }
}

// ---------------- time embedding chain ----------------
__global__ void __launch_bounds__(256) k_time1(const float* __restrict__ t,
                                               const float* __restrict__ t0_w,
                                               const float* __restrict__ t0_b) {
    __shared__ float emb[NFREQ];
    const int tid = threadIdx.x;  // 256
    {
        int i = tid & 127;
        float f   = expf(-9.210340371976184f * (float)i / 128.0f);
        float arg = t[0] * f;
        emb[tid] = (tid < 128) ? cosf(arg) : sinf(arg);
    }
    __syncthreads();
    const int warp = tid >> 5, lane = tid & 31;
    const int j = blockIdx.x*8 + warp;
    const float* w = t0_w + (size_t)j*NFREQ;
    float acc = 0.f;
#pragma unroll
    for (int i = 0; i < 8; i++) acc += emb[lane + i*32] * w[lane + i*32];
#pragma unroll
    for (int o = 16; o > 0; o >>= 1) acc += __shfl_xor_sync(0xffffffffu, acc, o);
    if (lane == 0) {
        float a = acc + t0_b[j];
        g_cpre[j] = a / (1.f + expf(-a));
    }
}

__global__ void __launch_bounds__(256) k_time2(const float* __restrict__ t2_w,
                                               const float* __restrict__ t2_b) {
    __shared__ float cp[EE];
    const int tid = threadIdx.x;
    for (int i = tid; i < EE; i += 256) cp[i] = g_cpre[i];
    __syncthreads();
    const int warp = tid >> 5, lane = tid & 31;
    const int j = blockIdx.x*8 + warp;
    const float* w = t2_w + (size_t)j*EE;
    float acc = 0.f;
#pragma unroll
    for (int i = 0; i < 24; i++) acc += cp[lane + i*32] * w[lane + i*32];
#pragma unroll
    for (int o = 16; o > 0; o >>= 1) acc += __shfl_xor_sync(0xffffffffu, acc, o);
    if (lane == 0) {
        float a = acc + t2_b[j];
        g_cs[j] = a / (1.f + expf(-a));
    }
}

// all adaLN vectors, one warp per row
__global__ void k_ada(const float* __restrict__ aw, const float* __restrict__ ab,
                      const float* __restrict__ fw, const float* __restrict__ fb) {
    const int gw   = (blockIdx.x*blockDim.x + threadIdx.x) >> 5;
    const int lane = threadIdx.x & 31;
    const int total = NDEPTH*6*EE + 2*EE;
    if (gw >= total) return;
    const float* wrow; float b;
    if (gw < NDEPTH*6*EE) { wrow = aw + (size_t)gw*EE; b = ab[gw]; }
    else { int r = gw - NDEPTH*6*EE; wrow = fw + (size_t)r*EE; b = fb[r]; }
    float acc = 0.f;
    for (int i = lane; i < EE; i += 32) acc += g_cs[i]*wrow[i];
#pragma unroll
    for (int o = 16; o > 0; o >>= 1) acc += __shfl_xor_sync(0xffffffffu, acc, o);
    if (lane == 0) g_ada[gw] = acc + b;
}

// ---------------- LayerNorm + adaLN modulation ----------------
__global__ void __launch_bounds__(256) k_lnmod(const float* __restrict__ x,
                                               int sh_off, int sc_off,
                                               float* __restrict__ out) {
    const int row = blockIdx.x, tid = threadIdx.x;
    const float* xr = x + (size_t)row*EE;
    float v0 = xr[tid], v1 = xr[tid+256], v2 = xr[tid+512];
    float s  = v0 + v1 + v2;
    float ss = v0*v0 + v1*v1 + v2*v2;
    __shared__ float rs[8], rss[8];
#pragma unroll
    for (int o = 16; o > 0; o >>= 1) {
        s  += __shfl_xor_sync(0xffffffffu, s,  o);
        ss += __shfl_xor_sync(0xffffffffu, ss, o);
    }
    if ((tid & 31) == 0) { rs[tid>>5] = s; rss[tid>>5] = ss; }
    __syncthreads();
    float st = 0.f, sst = 0.f;
#pragma unroll
    for (int i = 0; i < 8; i++) { st += rs[i]; sst += rss[i]; }
    const float mu   = st * (1.0f/EE);
    const float rstd = rsqrtf(sst*(1.0f/EE) - mu*mu + 1e-6f);
    const float* sh = g_ada + sh_off;
    const float* sc = g_ada + sc_off;
    float* orow = out + (size_t)row*EE;
    orow[tid]     = (v0-mu)*rstd*(1.f+sc[tid])     + sh[tid];
    orow[tid+256] = (v1-mu)*rstd*(1.f+sc[tid+256]) + sh[tid+256];
    orow[tid+512] = (v2-mu)*rstd*(1.f+sc[tid+512]) + sh[tid+512];
}

// ---------------- tf32 wmma GEMM, cp.async 3-stage pipeline, 256 threads ----------------
// C(MxN) = A(MxK) @ W(NxK)^T.  BN = 64 fixed, 8 warps, warp tile WTM x 32.
// EPI 0: out = acc+bias    EPI 1: out += g_ada[g_off+n]*(acc+bias)    EPI 2: out = gelu_tanh(acc+bias)
#define GBK 32
#define GLD 36

template<int BM, int AF4, int BF4>
__device__ __forceinline__ void g_issue(float* stage, const float* A, const float* W,
                                        int m0, int n0, int K, int k0, int tid) {
    float* sA = stage;
    float* sB = stage + BM*GLD;
#pragma unroll
    for (int i = 0; i < AF4; i++) {
        int f = tid + i*256;
        cp16(&sA[(f>>3)*GLD + ((f&7)<<2)], &A[(size_t)(m0 + (f>>3))*K + k0 + ((f&7)<<2)]);
    }
#pragma unroll
    for (int i = 0; i < BF4; i++) {
        int f = tid + i*256;
        cp16(&sB[(f>>3)*GLD + ((f&7)<<2)], &W[(size_t)(n0 + (f>>3))*K + k0 + ((f&7)<<2)]);
    }
    CP_COMMIT();
}

template<int EPI, int BM, int WTM>
__global__ void __launch_bounds__(256) k_gemm(
        const float* __restrict__ A, const float* __restrict__ W,
        const float* __restrict__ bias, int g_off,
        float* __restrict__ out, int M, int N, int K) {
    constexpr int BN  = 64;
    constexpr int WMC = BM/WTM;               // warps along M (4)
    constexpr int MI  = WTM/16;
    constexpr int NJ  = 2;                    // 32 cols per warp
    constexpr int STG = (BM+BN)*GLD;
    constexpr int AF4 = BM*8/256, BF4 = BN*8/256;
    constexpr int CLD = 36;

    extern __shared__ __align__(16) float smem[];
    const int tid = threadIdx.x, warp = tid >> 5, lane = tid & 31;
    const int wm = warp % WMC, wn = warp / WMC;
    const int m0 = blockIdx.y * BM;
    const int n0 = blockIdx.x * BN;

    wmma::fragment<wmma::accumulator,16,16,8,float> cf[MI][NJ];
#pragma unroll
    for (int i = 0; i < MI; i++)
#pragma unroll
        for (int j = 0; j < NJ; j++) wmma::fill_fragment(cf[i][j], 0.0f);

    const int nch = K / GBK;
    g_issue<BM,AF4,BF4>(smem,       A, W, m0, n0, K, 0,   tid);
    g_issue<BM,AF4,BF4>(smem + STG, A, W, m0, n0, K, GBK, tid);

    for (int ch = 0; ch < nch; ch++) {
        if (ch == nch-1) { CP_WAIT0(); } else { CP_WAIT1(); }
        __syncthreads();
        float* sA = smem + (ch % 3)*STG;
        float* sB = sA + BM*GLD;
#pragma unroll
        for (int kk = 0; kk < 4; kk++) {
            wmma::fragment<wmma::matrix_a,16,16,8,wmma::precision::tf32,wmma::row_major> af[MI];
            wmma::fragment<wmma::matrix_b,16,16,8,wmma::precision::tf32,wmma::col_major> bf[NJ];
#pragma unroll
            for (int i = 0; i < MI; i++) {
                wmma::load_matrix_sync(af[i], sA + (wm*WTM + i*16)*GLD + kk*8, GLD);
#pragma unroll
                for (int q = 0; q < af[i].num_elements; q++) af[i].x[q] = wmma::__float_to_tf32(af[i].x[q]);
            }
#pragma unroll
            for (int j = 0; j < NJ; j++) {
                wmma::load_matrix_sync(bf[j], sB + (wn*32 + j*16)*GLD + kk*8, GLD);
#pragma unroll
                for (int q = 0; q < bf[j].num_elements; q++) bf[j].x[q] = wmma::__float_to_tf32(bf[j].x[q]);
            }
#pragma unroll
            for (int i = 0; i < MI; i++)
#pragma unroll
                for (int j = 0; j < NJ; j++) wmma::mma_sync(cf[i][j], af[i], bf[j], cf[i][j]);
        }
        if (ch + 2 < nch)
            g_issue<BM,AF4,BF4>(smem + ((ch+2) % 3)*STG, A, W, m0, n0, K, (ch+2)*GBK, tid);
    }
    __syncthreads();
    // epilogue: stage per-warp WTM x 32 tile in smem
    float* cbuf = smem + warp*(WTM*CLD);
#pragma unroll
    for (int i = 0; i < MI; i++)
#pragma unroll
        for (int j = 0; j < NJ; j++)
            wmma::store_matrix_sync(cbuf + (i*16)*CLD + j*16, cf[i][j], CLD, wmma::mem_row_major);
    __syncwarp();
    const int ncol = n0 + wn*32 + lane;
    const float bv = bias ? bias[ncol] : 0.0f;
    const float gv = (EPI == 1) ? g_ada[g_off + ncol] : 0.0f;
#pragma unroll
    for (int r = 0; r < WTM; r++) {
        float v = cbuf[r*CLD + lane] + bv;
        size_t oi = (size_t)(m0 + wm*WTM + r)*N + ncol;
        if (EPI == 0) {
            out[oi] = v;
        } else if (EPI == 1) {
            out[oi] = out[oi] + gv * v;
        } else {
            float tn = tanhf(0.7978845608028654f*(v + 0.044715f*v*v*v));
            out[oi] = 0.5f*v*(1.0f + tn);
        }
    }
}

// ---------------- fused flash attention: one CTA per (q-tile 64, head), KV tile 64 ----------------
#define FLD  48
#define FLDS 68

__global__ void __launch_bounds__(128) k_flash() {
    extern __shared__ __align__(16) float fs[];
    float* sQ = fs;                 // 64 x 48
    float* sK = fs + 3072;          // 64 x 48
    float* sV = fs + 6144;          // 64 x 48
    float* sO = fs + 9216;          // 64 x 48
    float* sS = fs + 12288;         // 64 x 68 (64 cols used)
    float* sM = fs + 16640;         // 64
    float* sL = fs + 16704;         // 64

    const int tid  = threadIdx.x;   // 128
    const int warp = tid >> 5;
    const int qt = blockIdx.x, hh = blockIdx.y;
    const int l0 = qt*64;
    const float scale = 0.14433756729740643f;   // 48^-0.5
    const int rr = tid >> 1, hf = tid & 1;

    // load scaled Q tile (64 x 48)
#pragma unroll
    for (int i = 0; i < 6; i++) {
        int e = tid + i*128;
        int r = e/12, c4 = e%12;
        float4 v = *(const float4*)&g_qkv[(size_t)(l0+r)*(3*EE) + hh*144 + c4*4];
        v.x *= scale; v.y *= scale; v.z *= scale; v.w *= scale;
        *(float4*)&sQ[r*FLD + c4*4] = v;
    }
    for (int i = tid; i < 64*FLD; i += 128) sO[i] = 0.0f;
    if (tid < 64) { sM[tid] = -1e30f; sL[tid] = 0.0f; }

    // register prefetch of K/V tile 0 (64 rows)
    float4 pk[6], pv[6];
#pragma unroll
    for (int i = 0; i < 6; i++) {
        int e = tid + i*128;
        int r = e/12, c4 = e%12;
        pk[i] = *(const float4*)&g_qkv[(size_t)r*(3*EE) + hh*144 + 48 + c4*4];
        pv[i] = *(const float4*)&g_qkv[(size_t)r*(3*EE) + hh*144 + 96 + c4*4];
    }

    for (int mt = 0; mt < 16; mt++) {
        const int m0 = mt*64;
        __syncthreads();               // protects sK/sV reuse (+ init on iter 0)
#pragma unroll
        for (int i = 0; i < 6; i++) {
            int e = tid + i*128;
            int r = e/12, c4 = e%12;
            *(float4*)&sK[r*FLD + c4*4] = pk[i];
            *(float4*)&sV[r*FLD + c4*4] = pv[i];
        }
        __syncthreads();
        // prefetch next tile (overlaps with S/softmax/PV)
        if (mt < 15) {
            const int mn = m0 + 64;
#pragma unroll
            for (int i = 0; i < 6; i++) {
                int e = tid + i*128;
                int r = e/12, c4 = e%12;
                pk[i] = *(const float4*)&g_qkv[(size_t)(mn+r)*(3*EE) + hh*144 + 48 + c4*4];
                pv[i] = *(const float4*)&g_qkv[(size_t)(mn+r)*(3*EE) + hh*144 + 96 + c4*4];
            }
        }
        // S = Q @ K^T : warp handles rows warp*16..+15, cols 0..63
#pragma unroll
        for (int nt = 0; nt < 4; nt++) {
            wmma::fragment<wmma::accumulator,16,16,8,float> sc;
            wmma::fill_fragment(sc, 0.0f);
#pragma unroll
            for (int k = 0; k < 6; k++) {
                wmma::fragment<wmma::matrix_a,16,16,8,wmma::precision::tf32,wmma::row_major> af;
                wmma::fragment<wmma::matrix_b,16,16,8,wmma::precision::tf32,wmma::col_major> bf;
                wmma::load_matrix_sync(af, sQ + warp*16*FLD + k*8, FLD);
                wmma::load_matrix_sync(bf, sK + nt*16*FLD + k*8, FLD);
#pragma unroll
                for (int q = 0; q < af.num_elements; q++) af.x[q] = wmma::__float_to_tf32(af.x[q]);
#pragma unroll
                for (int q = 0; q < bf.num_elements; q++) bf.x[q] = wmma::__float_to_tf32(bf.x[q]);
                wmma::mma_sync(sc, af, bf, sc);
            }
            wmma::store_matrix_sync(sS + warp*16*FLDS + nt*16, sc, FLDS, wmma::mem_row_major);
        }
        __syncthreads();
        // bias add + online softmax: 2 threads per row, 32 cols each
        {
            const int c0 = hf*32;
            const __nv_bfloat16* bp = &g_bh[((size_t)hh << 20) + ((size_t)(l0+rr) << 10) + m0 + c0];
            float* srow = sS + rr*FLDS + c0;
            float v[32];
            float mloc = -1e30f;
#pragma unroll
            for (int c = 0; c < 32; c++) {
                v[c] = srow[c] + __bfloat162float(bp[c]);
                mloc = fmaxf(mloc, v[c]);
            }
            mloc = fmaxf(mloc, __shfl_xor_sync(0xffffffffu, mloc, 1));
            float mprev = sM[rr];
            float mnew  = fmaxf(mprev, mloc);
            float sum = 0.f;
#pragma unroll
            for (int c = 0; c < 32; c++) {
                float p = __expf(v[c] - mnew);
                srow[c] = p;
                sum += p;
            }
            sum += __shfl_xor_sync(0xffffffffu, sum, 1);
            float factor = __expf(mprev - mnew);
            if (hf == 0) { sM[rr] = mnew; sL[rr] = sL[rr]*factor + sum; }
            float* orow = sO + rr*FLD + hf*24;
#pragma unroll
            for (int c = 0; c < 24; c++) orow[c] *= factor;
        }
        __syncthreads();
        // O += P(64x64) @ V(64x48)
        {
            wmma::fragment<wmma::matrix_a,16,16,8,wmma::precision::tf32,wmma::row_major> pa[8];
#pragma unroll
            for (int kk = 0; kk < 8; kk++) {
                wmma::load_matrix_sync(pa[kk], sS + warp*16*FLDS + kk*8, FLDS);
#pragma unroll
                for (int q = 0; q < pa[kk].num_elements; q++) pa[kk].x[q] = wmma::__float_to_tf32(pa[kk].x[q]);
            }
#pragma unroll
            for (int j = 0; j < 3; j++) {
                wmma::fragment<wmma::accumulator,16,16,8,float> of;
                wmma::load_matrix_sync(of, sO + warp*16*FLD + j*16, FLD, wmma::mem_row_major);
#pragma unroll
                for (int kk = 0; kk < 8; kk++) {
                    wmma::fragment<wmma::matrix_b,16,16,8,wmma::precision::tf32,wmma::row_major> vb;
                    wmma::load_matrix_sync(vb, sV + kk*8*FLD + j*16, FLD);
#pragma unroll
                    for (int q = 0; q < vb.num_elements; q++) vb.x[q] = wmma::__float_to_tf32(vb.x[q]);
                    wmma::mma_sync(of, pa[kk], vb, of);
                }
                wmma::store_matrix_sync(sO + warp*16*FLD + j*16, of, FLD, wmma::mem_row_major);
            }
        }
    }
    __syncthreads();
    // normalize + write y[l, h*48+c]
    {
        float inv = 1.0f / sL[rr];
        const float* orow = sO + rr*FLD + hf*24;
        float* dst = g_y + (size_t)(l0+rr)*EE + hh*HDIM + hf*24;
#pragma unroll
        for (int c = 0; c < 24; c++) dst[c] = orow[c]*inv;
    }
}

// ---------------- driver ----------------
static const int SM_BIG   = 3*(128+64)*GLD*4;   // 82944 B  (3-stage 128x64) -> 2 CTA/SM
static const int SM_SMALL = 3*(64+64)*GLD*4;    // 55296 B  (3-stage 64x64)  -> 4 CTA/SM
static const int SM_FLASH = 16768*4;            // 67072 B

extern "C" void kernel_launch(void* const* d_in, const int* in_sizes, int n_in,
                              void* d_out, int out_size) {
    const float* z    = (const float*)d_in[0];
    const float* t    = (const float*)d_in[1];
    const float* bias = (const float*)d_in[2];
    const float* ln_g = (const float*)d_in[3];
    const float* ln_b = (const float*)d_in[4];
    const float* p2sw = (const float*)d_in[5];
    const float* t0w  = (const float*)d_in[6];
    const float* t0b  = (const float*)d_in[7];
    const float* t2w  = (const float*)d_in[8];
    const float* t2b  = (const float*)d_in[9];
    const float* pw   = (const float*)d_in[10];
    const float* ow   = (const float*)d_in[11];
    const float* ob   = (const float*)d_in[12];
    const float* aw   = (const float*)d_in[13];
    const float* ab   = (const float*)d_in[14];
    const float* f1w  = (const float*)d_in[15];
    const float* f1b  = (const float*)d_in[16];
    const float* f2w  = (const float*)d_in[17];
    const float* f2b  = (const float*)d_in[18];
    const float* faw  = (const float*)d_in[19];
    const float* fab  = (const float*)d_in[20];
    const float* fw   = (const float*)d_in[21];
    const float* fb   = (const float*)d_in[22];

    float *px, *ph, *pq, *py, *pm;
    cudaGetSymbolAddress((void**)&px, g_x);
    cudaGetSymbolAddress((void**)&ph, g_h);
    cudaGetSymbolAddress((void**)&pq, g_qkv);
    cudaGetSymbolAddress((void**)&py, g_y);
    cudaGetSymbolAddress((void**)&pm, g_mlp);

    cudaFuncSetAttribute(k_gemm<0,128,32>, cudaFuncAttributeMaxDynamicSharedMemorySize, SM_BIG);
    cudaFuncSetAttribute(k_gemm<2,128,32>, cudaFuncAttributeMaxDynamicSharedMemorySize, SM_BIG);
    cudaFuncSetAttribute(k_gemm<0,64,16>,  cudaFuncAttributeMaxDynamicSharedMemorySize, SM_SMALL);
    cudaFuncSetAttribute(k_gemm<1,64,16>,  cudaFuncAttributeMaxDynamicSharedMemorySize, SM_SMALL);
    cudaFuncSetAttribute(k_flash,          cudaFuncAttributeMaxDynamicSharedMemorySize, SM_FLASH);

    // ---- launch order chosen so launch #6 (ncu -s 5 -c 1) is the block-0 qkv GEMM ----
    k_prep<<<1, 128>>>(ln_g, ln_b, p2sw);                       // 1
    k_time1<<<96, 256>>>(t, t0w, t0b);                          // 2
    k_time2<<<96, 256>>>(t2w, t2b);                             // 3
    k_ada<<<4800, 256>>>(aw, ab, faw, fab);                     // 4
    k_lnmod<<<1024, 256>>>(z, 0, EE, ph);                       // 5 (block-0 LN reads z directly)
    k_gemm<0,128,32><<<dim3(36, 8), 256, SM_BIG>>>(             // 6  <-- profiled next round
        ph, pw, nullptr, 0, pq, LL, 3*EE, EE);
    k_bias<<<4096, 256>>>(bias);                                // 7
    k_copy<<<768, 1024>>>(z);                                   // 8
    k_flash<<<dim3(16, 16), 128, SM_FLASH>>>();                 // 9
    k_gemm<1,64,16><<<dim3(12, 16), 256, SM_SMALL>>>(py, ow, ob, 2*EE, px, LL, EE, EE);
    k_lnmod<<<1024, 256>>>(px, 3*EE, 4*EE, ph);
    k_gemm<2,128,32><<<dim3(48, 8), 256, SM_BIG>>>(ph, f1w, f1b, 0, pm, LL, MLPD, EE);
    k_gemm<1,64,16><<<dim3(12, 16), 256, SM_SMALL>>>(pm, f2w, f2b, 5*EE, px, LL, EE, MLPD);

    for (int d = 1; d < NDEPTH; d++) {
        const int base = d*6*EE;
        // attention branch
        k_lnmod<<<1024, 256>>>(px, base, base + EE, ph);
        k_gemm<0,128,32><<<dim3(36, 8), 256, SM_BIG>>>(ph, pw + (size_t)d*3*EE*EE, nullptr, 0,
                                                       pq, LL, 3*EE, EE);
        k_flash<<<dim3(16, 16), 128, SM_FLASH>>>();
        k_gemm<1,64,16><<<dim3(12, 16), 256, SM_SMALL>>>(py, ow + (size_t)d*EE*EE, ob + d*EE, base + 2*EE,
                                                         px, LL, EE, EE);
        // MLP branch
        k_lnmod<<<1024, 256>>>(px, base + 3*EE, base + 4*EE, ph);
        k_gemm<2,128,32><<<dim3(48, 8), 256, SM_BIG>>>(ph, f1w + (size_t)d*MLPD*EE, f1b + d*MLPD, 0,
                                                       pm, LL, MLPD, EE);
        k_gemm<1,64,16><<<dim3(12, 16), 256, SM_SMALL>>>(pm, f2w + (size_t)d*EE*MLPD, f2b + d*EE, base + 5*EE,
                                                         px, LL, EE, MLPD);
    }
    // final
    const int foff = NDEPTH*6*EE;
    k_lnmod<<<1024, 256>>>(px, foff, foff + EE, ph);
    k_gemm<0,64,16><<<dim3(12, 16), 256, SM_SMALL>>>(ph, fw, fb, 0, (float*)d_out, LL, EE, EE);
}

// round 15
// speedup vs baseline: 1.0725x; 1.0262x over previous
#include <cuda_runtime.h>
#include <cuda_bf16.h>
#include <mma.h>
#include <cmath>

using namespace nvcuda;

#define LL     1024
#define EE     768
#define PPD    128
#define HH     16
#define HDIM   48
#define NDEPTH 8
#define MLPD   3072
#define NFREQ  256

// ---------------- device-global scratch (no allocations allowed) ----------------
__device__ __align__(16) float g_x[LL*EE];
__device__ __align__(16) float g_h[LL*EE];
__device__ __align__(16) float g_qkv[LL*3*EE];
__device__ __align__(16) float g_y[LL*EE];
__device__ __align__(16) float g_mlp[LL*MLPD];
__device__ __align__(16) __nv_bfloat16 g_bh[(size_t)HH*LL*LL];   // 32 MB, [h][l][m]
__device__ float g_cs[EE];
__device__ float g_ada[NDEPTH*6*EE + 2*EE];
__device__ float g_Apw[HH*PPD];
__device__ float g_Spw[HH];
__device__ float g_Cpw[HH];

__device__ __forceinline__ void cp16(float* s, const float* g) {
    unsigned sa = (unsigned)__cvta_generic_to_shared(s);
    asm volatile("cp.async.cg.shared.global [%0], [%1], 16;\n" :: "r"(sa), "l"(g));
}
#define CP_COMMIT() asm volatile("cp.async.commit_group;\n" ::: "memory")
#define CP_WAIT0()  asm volatile("cp.async.wait_group 0;\n" ::: "memory")
#define CP_WAIT1()  asm volatile("cp.async.wait_group 1;\n" ::: "memory")

// round to tf32 (same op the per-fragment cvt loops used to do)
__device__ __forceinline__ float rtf(float x) { return wmma::__float_to_tf32(x); }

// ---------------- init ----------------
__global__ void k_copy(const float* __restrict__ z) {
    int i = blockIdx.x*1024 + threadIdx.x;
    g_x[i] = z[i];
}

__global__ void k_prep(const float* __restrict__ g, const float* __restrict__ beta,
                       const float* __restrict__ w) {
    const int p = threadIdx.x; // 128
    for (int h = 0; h < HH; h++)
        g_Apw[h*PPD + p] = g[p] * w[h*PPD + p];
    if (p < HH) {
        float s = 0.f, c = 0.f;
        for (int q = 0; q < PPD; q++) {
            s += g[q]    * w[p*PPD + q];
            c += beta[q] * w[p*PPD + q];
        }
        g_Spw[p] = s; g_Cpw[p] = c;
    }
}

// ---------------- bias LN + head projection: 512 MB read, one thread per row ----------------
__global__ void __launch_bounds__(256) k_bias(const float* __restrict__ bias) {
    __shared__ __align__(16) float sA[HH*PPD];
    __shared__ float sSh[HH], sCh[HH];
    const int tid = threadIdx.x;
    for (int i = tid; i < HH*PPD; i += 256) sA[i] = g_Apw[i];
    if (tid < HH) { sSh[tid] = g_Spw[tid]; sCh[tid] = g_Cpw[tid]; }
    __syncthreads();
    const int row = blockIdx.x*256 + tid;      // row = l*1024 + m
    const float* xr = bias + (size_t)row*PPD;
    float acc[HH];
#pragma unroll
    for (int h = 0; h < HH; h++) acc[h] = 0.f;
    float s = 0.f, ss = 0.f;
#pragma unroll
    for (int ch = 0; ch < 4; ch++) {
        float4 xv[8];
#pragma unroll
        for (int j = 0; j < 8; j++) xv[j] = *(const float4*)&xr[ch*32 + j*4];
#pragma unroll
        for (int j = 0; j < 8; j++) {
            s  += xv[j].x + xv[j].y + xv[j].z + xv[j].w;
            ss += xv[j].x*xv[j].x + xv[j].y*xv[j].y + xv[j].z*xv[j].z + xv[j].w*xv[j].w;
        }
#pragma unroll
        for (int h = 0; h < HH; h++) {
            const float* ar = &sA[h*PPD + ch*32];
            float a0 = 0.f;
#pragma unroll
            for (int j = 0; j < 8; j++) {
                float4 av = *(const float4*)&ar[j*4];
                a0 += xv[j].x*av.x + xv[j].y*av.y + xv[j].z*av.z + xv[j].w*av.w;
            }
            acc[h] += a0;
        }
    }
    const float mu   = s * (1.0f/PPD);
    const float rstd = rsqrtf(ss*(1.0f/PPD) - mu*mu + 1e-6f);
    const int l = row >> 10, m = row & 1023;
#pragma unroll
    for (int h = 0; h < HH; h++) {
        float v = rstd*(acc[h] - mu*sSh[h]) + sCh[h];
        g_bh[((size_t)h << 20) + ((size_t)l << 10) + m] = __float2bfloat16(v);
    }
}

// ---------------- time embedding chain, fused (each CTA recomputes cpre) ----------------
__global__ void __launch_bounds__(256) k_timeAll(const float* __restrict__ t,
                                                 const float* __restrict__ t0_w,
                                                 const float* __restrict__ t0_b,
                                                 const float* __restrict__ t2_w,
                                                 const float* __restrict__ t2_b) {
    __shared__ float emb[NFREQ];
    __shared__ float cp[EE];
    const int tid = threadIdx.x;  // 256
    {
        int i = tid & 127;
        float f   = expf(-9.210340371976184f * (float)i / 128.0f);
        float arg = t[0] * f;
        emb[tid] = (tid < 128) ? cosf(arg) : sinf(arg);
    }
    __syncthreads();
#pragma unroll
    for (int rep = 0; rep < 3; rep++) {
        const int j = tid + rep*256;
        const float* w = t0_w + (size_t)j*NFREQ;
        float a = t0_b[j];
#pragma unroll
        for (int i = 0; i < 64; i++) {
            float4 wv = *(const float4*)&w[i*4];
            a += emb[i*4]*wv.x + emb[i*4+1]*wv.y + emb[i*4+2]*wv.z + emb[i*4+3]*wv.w;
        }
        cp[j] = a / (1.f + expf(-a));
    }
    __syncthreads();
    const int warp = tid >> 5, lane = tid & 31;
    const int j = blockIdx.x*8 + warp;          // grid 96 -> 768 rows
    const float* w = t2_w + (size_t)j*EE;
    float acc = 0.f;
#pragma unroll
    for (int i = 0; i < 24; i++) acc += cp[lane + i*32] * w[lane + i*32];
#pragma unroll
    for (int o = 16; o > 0; o >>= 1) acc += __shfl_xor_sync(0xffffffffu, acc, o);
    if (lane == 0) {
        float a = acc + t2_b[j];
        g_cs[j] = a / (1.f + expf(-a));
    }
}

// all adaLN vectors, one warp per row
__global__ void k_ada(const float* __restrict__ aw, const float* __restrict__ ab,
                      const float* __restrict__ fw, const float* __restrict__ fb) {
    const int gw   = (blockIdx.x*blockDim.x + threadIdx.x) >> 5;
    const int lane = threadIdx.x & 31;
    const int total = NDEPTH*6*EE + 2*EE;
    if (gw >= total) return;
    const float* wrow; float b;
    if (gw < NDEPTH*6*EE) { wrow = aw + (size_t)gw*EE; b = ab[gw]; }
    else { int r = gw - NDEPTH*6*EE; wrow = fw + (size_t)r*EE; b = fb[r]; }
    float acc = 0.f;
    for (int i = lane; i < EE; i += 32) acc += g_cs[i]*wrow[i];
#pragma unroll
    for (int o = 16; o > 0; o >>= 1) acc += __shfl_xor_sync(0xffffffffu, acc, o);
    if (lane == 0) g_ada[gw] = acc + b;
}

// ---------------- LayerNorm + adaLN modulation (output pre-rounded to tf32) ----------------
__global__ void __launch_bounds__(256) k_lnmod(const float* __restrict__ x,
                                               int sh_off, int sc_off,
                                               float* __restrict__ out) {
    const int row = blockIdx.x, tid = threadIdx.x;
    const float* xr = x + (size_t)row*EE;
    float v0 = xr[tid], v1 = xr[tid+256], v2 = xr[tid+512];
    float s  = v0 + v1 + v2;
    float ss = v0*v0 + v1*v1 + v2*v2;
    __shared__ float rs[8], rss[8];
#pragma unroll
    for (int o = 16; o > 0; o >>= 1) {
        s  += __shfl_xor_sync(0xffffffffu, s,  o);
        ss += __shfl_xor_sync(0xffffffffu, ss, o);
    }
    if ((tid & 31) == 0) { rs[tid>>5] = s; rss[tid>>5] = ss; }
    __syncthreads();
    float st = 0.f, sst = 0.f;
#pragma unroll
    for (int i = 0; i < 8; i++) { st += rs[i]; sst += rss[i]; }
    const float mu   = st * (1.0f/EE);
    const float rstd = rsqrtf(sst*(1.0f/EE) - mu*mu + 1e-6f);
    const float* sh = g_ada + sh_off;
    const float* sc = g_ada + sc_off;
    float* orow = out + (size_t)row*EE;
    orow[tid]     = rtf((v0-mu)*rstd*(1.f+sc[tid])     + sh[tid]);
    orow[tid+256] = rtf((v1-mu)*rstd*(1.f+sc[tid+256]) + sh[tid+256]);
    orow[tid+512] = rtf((v2-mu)*rstd*(1.f+sc[tid+512]) + sh[tid+512]);
}

// ---------------- tf32 wmma GEMM, cp.async 3-stage pipeline, 256 threads ----------------
// A operand is pre-rounded to tf32 by its producer (lnmod / flash / gelu epilogue) -> no af cvt.
// EPI 0: out = acc+bias    EPI 1: out += g_ada[g_off+n]*(acc+bias)    EPI 2: out = rtf(gelu(acc+bias))
#define GBK 32
#define GLD 36

template<int BM, int AF4, int BF4>
__device__ __forceinline__ void g_issue(float* stage, const float* A, const float* W,
                                        int m0, int n0, int K, int k0, int tid) {
    float* sA = stage;
    float* sB = stage + BM*GLD;
#pragma unroll
    for (int i = 0; i < AF4; i++) {
        int f = tid + i*256;
        cp16(&sA[(f>>3)*GLD + ((f&7)<<2)], &A[(size_t)(m0 + (f>>3))*K + k0 + ((f&7)<<2)]);
    }
#pragma unroll
    for (int i = 0; i < BF4; i++) {
        int f = tid + i*256;
        cp16(&sB[(f>>3)*GLD + ((f&7)<<2)], &W[(size_t)(n0 + (f>>3))*K + k0 + ((f&7)<<2)]);
    }
    CP_COMMIT();
}

template<int EPI, int BM, int WTM>
__global__ void __launch_bounds__(256) k_gemm(
        const float* __restrict__ A, const float* __restrict__ W,
        const float* __restrict__ bias, int g_off,
        float* __restrict__ out, int M, int N, int K) {
    constexpr int BN  = 64;
    constexpr int WMC = BM/WTM;
    constexpr int MI  = WTM/16;
    constexpr int NJ  = 2;
    constexpr int STG = (BM+BN)*GLD;
    constexpr int AF4 = BM*8/256, BF4 = BN*8/256;
    constexpr int CLD = 36;

    extern __shared__ __align__(16) float smem[];
    const int tid = threadIdx.x, warp = tid >> 5, lane = tid & 31;
    const int wm = warp % WMC, wn = warp / WMC;
    const int m0 = blockIdx.y * BM;
    const int n0 = blockIdx.x * BN;

    wmma::fragment<wmma::accumulator,16,16,8,float> cf[MI][NJ];
#pragma unroll
    for (int i = 0; i < MI; i++)
#pragma unroll
        for (int j = 0; j < NJ; j++) wmma::fill_fragment(cf[i][j], 0.0f);

    const int nch = K / GBK;
    g_issue<BM,AF4,BF4>(smem,       A, W, m0, n0, K, 0,   tid);
    g_issue<BM,AF4,BF4>(smem + STG, A, W, m0, n0, K, GBK, tid);

    for (int ch = 0; ch < nch; ch++) {
        if (ch == nch-1) { CP_WAIT0(); } else { CP_WAIT1(); }
        __syncthreads();
        float* sA = smem + (ch % 3)*STG;
        float* sB = sA + BM*GLD;
#pragma unroll
        for (int kk = 0; kk < 4; kk++) {
            wmma::fragment<wmma::matrix_a,16,16,8,wmma::precision::tf32,wmma::row_major> af[MI];
            wmma::fragment<wmma::matrix_b,16,16,8,wmma::precision::tf32,wmma::col_major> bf[NJ];
#pragma unroll
            for (int i = 0; i < MI; i++)
                wmma::load_matrix_sync(af[i], sA + (wm*WTM + i*16)*GLD + kk*8, GLD);   // pre-rounded
#pragma unroll
            for (int j = 0; j < NJ; j++) {
                wmma::load_matrix_sync(bf[j], sB + (wn*32 + j*16)*GLD + kk*8, GLD);
#pragma unroll
                for (int q = 0; q < bf[j].num_elements; q++) bf[j].x[q] = wmma::__float_to_tf32(bf[j].x[q]);
            }
#pragma unroll
            for (int i = 0; i < MI; i++)
#pragma unroll
                for (int j = 0; j < NJ; j++) wmma::mma_sync(cf[i][j], af[i], bf[j], cf[i][j]);
        }
        if (ch + 2 < nch)
            g_issue<BM,AF4,BF4>(smem + ((ch+2) % 3)*STG, A, W, m0, n0, K, (ch+2)*GBK, tid);
    }
    __syncthreads();
    float* cbuf = smem + warp*(WTM*CLD);
#pragma unroll
    for (int i = 0; i < MI; i++)
#pragma unroll
        for (int j = 0; j < NJ; j++)
            wmma::store_matrix_sync(cbuf + (i*16)*CLD + j*16, cf[i][j], CLD, wmma::mem_row_major);
    __syncwarp();
    const int ncol = n0 + wn*32 + lane;
    const float bv = bias ? bias[ncol] : 0.0f;
    const float gv = (EPI == 1) ? g_ada[g_off + ncol] : 0.0f;
#pragma unroll
    for (int r = 0; r < WTM; r++) {
        float v = cbuf[r*CLD + lane] + bv;
        size_t oi = (size_t)(m0 + wm*WTM + r)*N + ncol;
        if (EPI == 0) {
            out[oi] = v;
        } else if (EPI == 1) {
            out[oi] = out[oi] + gv * v;
        } else {
            float tn = tanhf(0.7978845608028654f*(v + 0.044715f*v*v*v));
            out[oi] = rtf(0.5f*v*(1.0f + tn));      // pre-round: fc2's A operand
        }
    }
}

// ---------------- fused flash attention: all smem tiles pre-rounded to tf32, no cvt loops ----------------
#define FLD  48
#define FLDS 68

__global__ void __launch_bounds__(128) k_flash() {
    extern __shared__ __align__(16) float fs[];
    float* sQ = fs;                 // 64 x 48
    float* sK = fs + 3072;          // 64 x 48
    float* sV = fs + 6144;          // 64 x 48
    float* sO = fs + 9216;          // 64 x 48
    float* sS = fs + 12288;         // 64 x 68 (64 cols used)
    float* sM = fs + 16640;         // 64
    float* sL = fs + 16704;         // 64

    const int tid  = threadIdx.x;   // 128
    const int warp = tid >> 5;
    const int qt = blockIdx.x, hh = blockIdx.y;
    const int l0 = qt*64;
    const float scale = 0.14433756729740643f;   // 48^-0.5
    const int rr = tid >> 1, hf = tid & 1;

    // load scaled Q tile (64 x 48), rounded to tf32
#pragma unroll
    for (int i = 0; i < 6; i++) {
        int e = tid + i*128;
        int r = e/12, c4 = e%12;
        float4 v = *(const float4*)&g_qkv[(size_t)(l0+r)*(3*EE) + hh*144 + c4*4];
        v.x = rtf(v.x*scale); v.y = rtf(v.y*scale); v.z = rtf(v.z*scale); v.w = rtf(v.w*scale);
        *(float4*)&sQ[r*FLD + c4*4] = v;
    }
    for (int i = tid; i < 64*FLD; i += 128) sO[i] = 0.0f;
    if (tid < 64) { sM[tid] = -1e30f; sL[tid] = 0.0f; }

    // register prefetch of K/V tile 0 (64 rows)
    float4 pk[6], pv[6];
#pragma unroll
    for (int i = 0; i < 6; i++) {
        int e = tid + i*128;
        int r = e/12, c4 = e%12;
        pk[i] = *(const float4*)&g_qkv[(size_t)r*(3*EE) + hh*144 + 48 + c4*4];
        pv[i] = *(const float4*)&g_qkv[(size_t)r*(3*EE) + hh*144 + 96 + c4*4];
    }

    for (int mt = 0; mt < 16; mt++) {
        const int m0 = mt*64;
        __syncthreads();               // protects sK/sV reuse (+ init on iter 0)
#pragma unroll
        for (int i = 0; i < 6; i++) {
            int e = tid + i*128;
            int r = e/12, c4 = e%12;
            float4 kk4 = pk[i], vv4 = pv[i];
            kk4.x=rtf(kk4.x); kk4.y=rtf(kk4.y); kk4.z=rtf(kk4.z); kk4.w=rtf(kk4.w);
            vv4.x=rtf(vv4.x); vv4.y=rtf(vv4.y); vv4.z=rtf(vv4.z); vv4.w=rtf(vv4.w);
            *(float4*)&sK[r*FLD + c4*4] = kk4;
            *(float4*)&sV[r*FLD + c4*4] = vv4;
        }
        __syncthreads();
        // prefetch next tile (overlaps with S/softmax/PV)
        if (mt < 15) {
            const int mn = m0 + 64;
#pragma unroll
            for (int i = 0; i < 6; i++) {
                int e = tid + i*128;
                int r = e/12, c4 = e%12;
                pk[i] = *(const float4*)&g_qkv[(size_t)(mn+r)*(3*EE) + hh*144 + 48 + c4*4];
                pv[i] = *(const float4*)&g_qkv[(size_t)(mn+r)*(3*EE) + hh*144 + 96 + c4*4];
            }
        }
        // S = Q @ K^T : warp handles rows warp*16..+15, cols 0..63
#pragma unroll
        for (int nt = 0; nt < 4; nt++) {
            wmma::fragment<wmma::accumulator,16,16,8,float> sc;
            wmma::fill_fragment(sc, 0.0f);
#pragma unroll
            for (int k = 0; k < 6; k++) {
                wmma::fragment<wmma::matrix_a,16,16,8,wmma::precision::tf32,wmma::row_major> af;
                wmma::fragment<wmma::matrix_b,16,16,8,wmma::precision::tf32,wmma::col_major> bf;
                wmma::load_matrix_sync(af, sQ + warp*16*FLD + k*8, FLD);
                wmma::load_matrix_sync(bf, sK + nt*16*FLD + k*8, FLD);
                wmma::mma_sync(sc, af, bf, sc);
            }
            wmma::store_matrix_sync(sS + warp*16*FLDS + nt*16, sc, FLDS, wmma::mem_row_major);
        }
        __syncthreads();
        // bias add + online softmax: 2 threads per row, 32 cols each
        {
            const int c0 = hf*32;
            const __nv_bfloat16* bp = &g_bh[((size_t)hh << 20) + ((size_t)(l0+rr) << 10) + m0 + c0];
            float* srow = sS + rr*FLDS + c0;
            float v[32];
            float mloc = -1e30f;
#pragma unroll
            for (int c = 0; c < 32; c++) {
                v[c] = srow[c] + __bfloat162float(bp[c]);
                mloc = fmaxf(mloc, v[c]);
            }
            mloc = fmaxf(mloc, __shfl_xor_sync(0xffffffffu, mloc, 1));
            float mprev = sM[rr];
            float mnew  = fmaxf(mprev, mloc);
            float sum = 0.f;
#pragma unroll
            for (int c = 0; c < 32; c++) {
                float p = __expf(v[c] - mnew);
                srow[c] = rtf(p);          // P pre-rounded for the PV mma
                sum += p;                  // sum in fp32 (same as before)
            }
            sum += __shfl_xor_sync(0xffffffffu, sum, 1);
            float factor = __expf(mprev - mnew);
            if (hf == 0) { sM[rr] = mnew; sL[rr] = sL[rr]*factor + sum; }
            float* orow = sO + rr*FLD + hf*24;
#pragma unroll
            for (int c = 0; c < 24; c++) orow[c] *= factor;
        }
        __syncthreads();
        // O += P(64x64) @ V(64x48)
        {
            wmma::fragment<wmma::matrix_a,16,16,8,wmma::precision::tf32,wmma::row_major> pa[8];
#pragma unroll
            for (int kk = 0; kk < 8; kk++)
                wmma::load_matrix_sync(pa[kk], sS + warp*16*FLDS + kk*8, FLDS);
#pragma unroll
            for (int j = 0; j < 3; j++) {
                wmma::fragment<wmma::accumulator,16,16,8,float> of;
                wmma::load_matrix_sync(of, sO + warp*16*FLD + j*16, FLD, wmma::mem_row_major);
#pragma unroll
                for (int kk = 0; kk < 8; kk++) {
                    wmma::fragment<wmma::matrix_b,16,16,8,wmma::precision::tf32,wmma::row_major> vb;
                    wmma::load_matrix_sync(vb, sV + kk*8*FLD + j*16, FLD);
                    wmma::mma_sync(of, pa[kk], vb, of);
                }
                wmma::store_matrix_sync(sO + warp*16*FLD + j*16, of, FLD, wmma::mem_row_major);
            }
        }
    }
    __syncthreads();
    // normalize + write y[l, h*48+c] (rounded: y is the A operand of o-proj)
    {
        float inv = 1.0f / sL[rr];
        const float* orow = sO + rr*FLD + hf*24;
        float* dst = g_y + (size_t)(l0+rr)*EE + hh*HDIM + hf*24;
#pragma unroll
        for (int c = 0; c < 24; c++) dst[c] = rtf(orow[c]*inv);
    }
}

// ---------------- driver ----------------
static const int SM_BIG   = 3*(128+64)*GLD*4;   // 82944 B
static const int SM_SMALL = 3*(64+64)*GLD*4;    // 55296 B
static const int SM_FLASH = 16768*4;            // 67072 B

extern "C" void kernel_launch(void* const* d_in, const int* in_sizes, int n_in,
                              void* d_out, int out_size) {
    const float* z    = (const float*)d_in[0];
    const float* t    = (const float*)d_in[1];
    const float* bias = (const float*)d_in[2];
    const float* ln_g = (const float*)d_in[3];
    const float* ln_b = (const float*)d_in[4];
    const float* p2sw = (const float*)d_in[5];
    const float* t0w  = (const float*)d_in[6];
    const float* t0b  = (const float*)d_in[7];
    const float* t2w  = (const float*)d_in[8];
    const float* t2b  = (const float*)d_in[9];
    const float* pw   = (const float*)d_in[10];
    const float* ow   = (const float*)d_in[11];
    const float* ob   = (const float*)d_in[12];
    const float* aw   = (const float*)d_in[13];
    const float* ab   = (const float*)d_in[14];
    const float* f1w  = (const float*)d_in[15];
    const float* f1b  = (const float*)d_in[16];
    const float* f2w  = (const float*)d_in[17];
    const float* f2b  = (const float*)d_in[18];
    const float* faw  = (const float*)d_in[19];
    const float* fab  = (const float*)d_in[20];
    const float* fw   = (const float*)d_in[21];
    const float* fb   = (const float*)d_in[22];

    float *px, *ph, *pq, *py, *pm;
    cudaGetSymbolAddress((void**)&px, g_x);
    cudaGetSymbolAddress((void**)&ph, g_h);
    cudaGetSymbolAddress((void**)&pq, g_qkv);
    cudaGetSymbolAddress((void**)&py, g_y);
    cudaGetSymbolAddress((void**)&pm, g_mlp);

    cudaFuncSetAttribute(k_gemm<0,128,32>, cudaFuncAttributeMaxDynamicSharedMemorySize, SM_BIG);
    cudaFuncSetAttribute(k_gemm<2,128,32>, cudaFuncAttributeMaxDynamicSharedMemorySize, SM_BIG);
    cudaFuncSetAttribute(k_gemm<0,64,16>,  cudaFuncAttributeMaxDynamicSharedMemorySize, SM_SMALL);
    cudaFuncSetAttribute(k_gemm<1,64,16>,  cudaFuncAttributeMaxDynamicSharedMemorySize, SM_SMALL);
    cudaFuncSetAttribute(k_flash,          cudaFuncAttributeMaxDynamicSharedMemorySize, SM_FLASH);

    // ---- ncu captures our 4th launch (evidence: R7/R8/R12/R14) -> slot 4 = qkv GEMM ----
    k_timeAll<<<96, 256>>>(t, t0w, t0b, t2w, t2b);              // 1
    k_ada<<<4800, 256>>>(aw, ab, faw, fab);                     // 2
    k_lnmod<<<1024, 256>>>(z, 0, EE, ph);                       // 3 (block-0 LN reads z directly)
    k_gemm<0,128,32><<<dim3(36, 8), 256, SM_BIG>>>(             // 4  <-- profiled next round
        ph, pw, nullptr, 0, pq, LL, 3*EE, EE);
    k_prep<<<1, 128>>>(ln_g, ln_b, p2sw);                       // 5
    k_bias<<<4096, 256>>>(bias);                                // 6
    k_copy<<<768, 1024>>>(z);                                   // 7
    k_flash<<<dim3(16, 16), 128, SM_FLASH>>>();                 // 8
    k_gemm<1,64,16><<<dim3(12, 16), 256, SM_SMALL>>>(py, ow, ob, 2*EE, px, LL, EE, EE);
    k_lnmod<<<1024, 256>>>(px, 3*EE, 4*EE, ph);
    k_gemm<2,128,32><<<dim3(48, 8), 256, SM_BIG>>>(ph, f1w, f1b, 0, pm, LL, MLPD, EE);
    k_gemm<1,64,16><<<dim3(12, 16), 256, SM_SMALL>>>(pm, f2w, f2b, 5*EE, px, LL, EE, MLPD);

    for (int d = 1; d < NDEPTH; d++) {
        const int base = d*6*EE;
        // attention branch
        k_lnmod<<<1024, 256>>>(px, base, base + EE, ph);
        k_gemm<0,128,32><<<dim3(36, 8), 256, SM_BIG>>>(ph, pw + (size_t)d*3*EE*EE, nullptr, 0,
                                                       pq, LL, 3*EE, EE);
        k_flash<<<dim3(16, 16), 128, SM_FLASH>>>();
        k_gemm<1,64,16><<<dim3(12, 16), 256, SM_SMALL>>>(py, ow + (size_t)d*EE*EE, ob + d*EE, base + 2*EE,
                                                         px, LL, EE, EE);
        // MLP branch
        k_lnmod<<<1024, 256>>>(px, base + 3*EE, base + 4*EE, ph);
        k_gemm<2,128,32><<<dim3(48, 8), 256, SM_BIG>>>(ph, f1w + (size_t)d*MLPD*EE, f1b + d*MLPD, 0,
                                                       pm, LL, MLPD, EE);
        k_gemm<1,64,16><<<dim3(12, 16), 256, SM_SMALL>>>(pm, f2w + (size_t)d*EE*MLPD, f2b + d*EE, base + 5*EE,
                                                         px, LL, EE, MLPD);
    }
    // final
    const int foff = NDEPTH*6*EE;
    k_lnmod<<<1024, 256>>>(px, foff, foff + EE, ph);
    k_gemm<0,64,16><<<dim3(12, 16), 256, SM_SMALL>>>(ph, fw, fb, 0, (float*)d_out, LL, EE, EE);
}

// round 16
// speedup vs baseline: 1.0966x; 1.0224x over previous
#include <cuda_runtime.h>
#include <cuda_bf16.h>
#include <mma.h>
#include <cmath>

using namespace nvcuda;

#define LL     1024
#define EE     768
#define PPD    128
#define HH     16
#define HDIM   48
#define NDEPTH 8
#define MLPD   3072
#define NFREQ  256

// ---------------- device-global scratch (no allocations allowed) ----------------
__device__ __align__(16) float g_x[LL*EE];
__device__ __align__(16) float g_h[LL*EE];
__device__ __align__(16) float g_qkv[LL*3*EE];
__device__ __align__(16) float g_y[LL*EE];
__device__ __align__(16) float g_mlp[LL*MLPD];
__device__ __align__(16) __nv_bfloat16 g_bh[(size_t)HH*LL*LL];   // 32 MB, [h][l][m]
__device__ float g_cs[EE];
__device__ float g_ada[NDEPTH*6*EE + 2*EE];
__device__ float g_Apw[HH*PPD];
__device__ float g_Spw[HH];
__device__ float g_Cpw[HH];

__device__ __forceinline__ void cp16(float* s, const float* g) {
    unsigned sa = (unsigned)__cvta_generic_to_shared(s);
    asm volatile("cp.async.cg.shared.global [%0], [%1], 16;\n" :: "r"(sa), "l"(g));
}
#define CP_COMMIT() asm volatile("cp.async.commit_group;\n" ::: "memory")
#define CP_WAIT0()  asm volatile("cp.async.wait_group 0;\n" ::: "memory")
#define CP_WAIT1()  asm volatile("cp.async.wait_group 1;\n" ::: "memory")

// round to tf32 (same op the per-fragment cvt loops used to do)
__device__ __forceinline__ float rtf(float x) { return wmma::__float_to_tf32(x); }

// ---------------- init ----------------
__global__ void k_copy(const float* __restrict__ z) {
    int i = blockIdx.x*1024 + threadIdx.x;
    g_x[i] = z[i];
}

__global__ void k_prep(const float* __restrict__ g, const float* __restrict__ beta,
                       const float* __restrict__ w) {
    const int p = threadIdx.x; // 128
    for (int h = 0; h < HH; h++)
        g_Apw[h*PPD + p] = g[p] * w[h*PPD + p];
    if (p < HH) {
        float s = 0.f, c = 0.f;
        for (int q = 0; q < PPD; q++) {
            s += g[q]    * w[p*PPD + q];
            c += beta[q] * w[p*PPD + q];
        }
        g_Spw[p] = s; g_Cpw[p] = c;
    }
}

// ---------------- bias LN + head projection: 512 MB read, one thread per row ----------------
__global__ void __launch_bounds__(256) k_bias(const float* __restrict__ bias) {
    __shared__ __align__(16) float sA[HH*PPD];
    __shared__ float sSh[HH], sCh[HH];
    const int tid = threadIdx.x;
    for (int i = tid; i < HH*PPD; i += 256) sA[i] = g_Apw[i];
    if (tid < HH) { sSh[tid] = g_Spw[tid]; sCh[tid] = g_Cpw[tid]; }
    __syncthreads();
    const int row = blockIdx.x*256 + tid;      // row = l*1024 + m
    const float* xr = bias + (size_t)row*PPD;
    float acc[HH];
#pragma unroll
    for (int h = 0; h < HH; h++) acc[h] = 0.f;
    float s = 0.f, ss = 0.f;
#pragma unroll
    for (int ch = 0; ch < 4; ch++) {
        float4 xv[8];
#pragma unroll
        for (int j = 0; j < 8; j++) xv[j] = *(const float4*)&xr[ch*32 + j*4];
#pragma unroll
        for (int j = 0; j < 8; j++) {
            s  += xv[j].x + xv[j].y + xv[j].z + xv[j].w;
            ss += xv[j].x*xv[j].x + xv[j].y*xv[j].y + xv[j].z*xv[j].z + xv[j].w*xv[j].w;
        }
#pragma unroll
        for (int h = 0; h < HH; h++) {
            const float* ar = &sA[h*PPD + ch*32];
            float a0 = 0.f;
#pragma unroll
            for (int j = 0; j < 8; j++) {
                float4 av = *(const float4*)&ar[j*4];
                a0 += xv[j].x*av.x + xv[j].y*av.y + xv[j].z*av.z + xv[j].w*av.w;
            }
            acc[h] += a0;
        }
    }
    const float mu   = s * (1.0f/PPD);
    const float rstd = rsqrtf(ss*(1.0f/PPD) - mu*mu + 1e-6f);
    const int l = row >> 10, m = row & 1023;
#pragma unroll
    for (int h = 0; h < HH; h++) {
        float v = rstd*(acc[h] - mu*sSh[h]) + sCh[h];
        g_bh[((size_t)h << 20) + ((size_t)l << 10) + m] = __float2bfloat16(v);
    }
}

// ---------------- time embedding chain, fused (each CTA recomputes cpre) ----------------
__global__ void __launch_bounds__(256) k_timeAll(const float* __restrict__ t,
                                                 const float* __restrict__ t0_w,
                                                 const float* __restrict__ t0_b,
                                                 const float* __restrict__ t2_w,
                                                 const float* __restrict__ t2_b) {
    __shared__ float emb[NFREQ];
    __shared__ float cp[EE];
    const int tid = threadIdx.x;  // 256
    {
        int i = tid & 127;
        float f   = expf(-9.210340371976184f * (float)i / 128.0f);
        float arg = t[0] * f;
        emb[tid] = (tid < 128) ? cosf(arg) : sinf(arg);
    }
    __syncthreads();
#pragma unroll
    for (int rep = 0; rep < 3; rep++) {
        const int j = tid + rep*256;
        const float* w = t0_w + (size_t)j*NFREQ;
        float a = t0_b[j];
#pragma unroll
        for (int i = 0; i < 64; i++) {
            float4 wv = *(const float4*)&w[i*4];
            a += emb[i*4]*wv.x + emb[i*4+1]*wv.y + emb[i*4+2]*wv.z + emb[i*4+3]*wv.w;
        }
        cp[j] = a / (1.f + expf(-a));
    }
    __syncthreads();
    const int warp = tid >> 5, lane = tid & 31;
    const int j = blockIdx.x*8 + warp;          // grid 96 -> 768 rows
    const float* w = t2_w + (size_t)j*EE;
    float acc = 0.f;
#pragma unroll
    for (int i = 0; i < 24; i++) acc += cp[lane + i*32] * w[lane + i*32];
#pragma unroll
    for (int o = 16; o > 0; o >>= 1) acc += __shfl_xor_sync(0xffffffffu, acc, o);
    if (lane == 0) {
        float a = acc + t2_b[j];
        g_cs[j] = a / (1.f + expf(-a));
    }
}

// all adaLN vectors, one warp per row
__global__ void k_ada(const float* __restrict__ aw, const float* __restrict__ ab,
                      const float* __restrict__ fw, const float* __restrict__ fb) {
    const int gw   = (blockIdx.x*blockDim.x + threadIdx.x) >> 5;
    const int lane = threadIdx.x & 31;
    const int total = NDEPTH*6*EE + 2*EE;
    if (gw >= total) return;
    const float* wrow; float b;
    if (gw < NDEPTH*6*EE) { wrow = aw + (size_t)gw*EE; b = ab[gw]; }
    else { int r = gw - NDEPTH*6*EE; wrow = fw + (size_t)r*EE; b = fb[r]; }
    float acc = 0.f;
    for (int i = lane; i < EE; i += 32) acc += g_cs[i]*wrow[i];
#pragma unroll
    for (int o = 16; o > 0; o >>= 1) acc += __shfl_xor_sync(0xffffffffu, acc, o);
    if (lane == 0) g_ada[gw] = acc + b;
}

// ---------------- LayerNorm + adaLN modulation (output pre-rounded to tf32) ----------------
__global__ void __launch_bounds__(256) k_lnmod(const float* __restrict__ x,
                                               int sh_off, int sc_off,
                                               float* __restrict__ out) {
    const int row = blockIdx.x, tid = threadIdx.x;
    const float* xr = x + (size_t)row*EE;
    float v0 = xr[tid], v1 = xr[tid+256], v2 = xr[tid+512];
    float s  = v0 + v1 + v2;
    float ss = v0*v0 + v1*v1 + v2*v2;
    __shared__ float rs[8], rss[8];
#pragma unroll
    for (int o = 16; o > 0; o >>= 1) {
        s  += __shfl_xor_sync(0xffffffffu, s,  o);
        ss += __shfl_xor_sync(0xffffffffu, ss, o);
    }
    if ((tid & 31) == 0) { rs[tid>>5] = s; rss[tid>>5] = ss; }
    __syncthreads();
    float st = 0.f, sst = 0.f;
#pragma unroll
    for (int i = 0; i < 8; i++) { st += rs[i]; sst += rss[i]; }
    const float mu   = st * (1.0f/EE);
    const float rstd = rsqrtf(sst*(1.0f/EE) - mu*mu + 1e-6f);
    const float* sh = g_ada + sh_off;
    const float* sc = g_ada + sc_off;
    float* orow = out + (size_t)row*EE;
    orow[tid]     = rtf((v0-mu)*rstd*(1.f+sc[tid])     + sh[tid]);
    orow[tid+256] = rtf((v1-mu)*rstd*(1.f+sc[tid+256]) + sh[tid+256]);
    orow[tid+512] = rtf((v2-mu)*rstd*(1.f+sc[tid+512]) + sh[tid+512]);
}

// ---------------- tf32 wmma GEMM, cp.async 2-stage pipeline, 256 threads, 3 CTA/SM ----------------
// A operand pre-rounded to tf32 by producer. EPI 0: out=acc+bias   EPI 1: out += g_ada[g_off+n]*(acc+bias)
// EPI 2: out = rtf(gelu(acc+bias))
#define GBK 32
#define GLD 36

template<int BM, int AF4, int BF4>
__device__ __forceinline__ void g_issue(float* stage, const float* A, const float* W,
                                        int m0, int n0, int K, int k0, int tid) {
    float* sA = stage;
    float* sB = stage + BM*GLD;
#pragma unroll
    for (int i = 0; i < AF4; i++) {
        int f = tid + i*256;
        cp16(&sA[(f>>3)*GLD + ((f&7)<<2)], &A[(size_t)(m0 + (f>>3))*K + k0 + ((f&7)<<2)]);
    }
#pragma unroll
    for (int i = 0; i < BF4; i++) {
        int f = tid + i*256;
        cp16(&sB[(f>>3)*GLD + ((f&7)<<2)], &W[(size_t)(n0 + (f>>3))*K + k0 + ((f&7)<<2)]);
    }
    CP_COMMIT();
}

template<int EPI, int BM, int WTM>
__global__ void __launch_bounds__(256, 3) k_gemm(
        const float* __restrict__ A, const float* __restrict__ W,
        const float* __restrict__ bias, int g_off,
        float* __restrict__ out, int M, int N, int K) {
    constexpr int BN  = 64;
    constexpr int WMC = BM/WTM;
    constexpr int MI  = WTM/16;
    constexpr int NJ  = 2;
    constexpr int STG = (BM+BN)*GLD;
    constexpr int AF4 = BM*8/256, BF4 = BN*8/256;
    constexpr int CLD = 36;

    extern __shared__ __align__(16) float smem[];
    const int tid = threadIdx.x, warp = tid >> 5, lane = tid & 31;
    const int wm = warp % WMC, wn = warp / WMC;
    const int m0 = blockIdx.y * BM;
    const int n0 = blockIdx.x * BN;

    wmma::fragment<wmma::accumulator,16,16,8,float> cf[MI][NJ];
#pragma unroll
    for (int i = 0; i < MI; i++)
#pragma unroll
        for (int j = 0; j < NJ; j++) wmma::fill_fragment(cf[i][j], 0.0f);

    const int nch = K / GBK;
    g_issue<BM,AF4,BF4>(smem,       A, W, m0, n0, K, 0,   tid);
    g_issue<BM,AF4,BF4>(smem + STG, A, W, m0, n0, K, GBK, tid);

    for (int ch = 0; ch < nch; ch++) {
        if (ch == nch-1) { CP_WAIT0(); } else { CP_WAIT1(); }
        __syncthreads();
        float* sA = smem + (ch & 1)*STG;
        float* sB = sA + BM*GLD;
#pragma unroll
        for (int kk = 0; kk < 4; kk++) {
            wmma::fragment<wmma::matrix_a,16,16,8,wmma::precision::tf32,wmma::row_major> af[MI];
            wmma::fragment<wmma::matrix_b,16,16,8,wmma::precision::tf32,wmma::col_major> bf[NJ];
#pragma unroll
            for (int i = 0; i < MI; i++)
                wmma::load_matrix_sync(af[i], sA + (wm*WTM + i*16)*GLD + kk*8, GLD);   // pre-rounded
#pragma unroll
            for (int j = 0; j < NJ; j++) {
                wmma::load_matrix_sync(bf[j], sB + (wn*32 + j*16)*GLD + kk*8, GLD);
#pragma unroll
                for (int q = 0; q < bf[j].num_elements; q++) bf[j].x[q] = wmma::__float_to_tf32(bf[j].x[q]);
            }
#pragma unroll
            for (int i = 0; i < MI; i++)
#pragma unroll
                for (int j = 0; j < NJ; j++) wmma::mma_sync(cf[i][j], af[i], bf[j], cf[i][j]);
        }
        __syncthreads();                                   // all warps done reading stage ch&1
        if (ch + 2 < nch)
            g_issue<BM,AF4,BF4>(smem + (ch & 1)*STG, A, W, m0, n0, K, (ch+2)*GBK, tid);
    }
    // epilogue
    float* cbuf = smem + warp*(WTM*CLD);
#pragma unroll
    for (int i = 0; i < MI; i++)
#pragma unroll
        for (int j = 0; j < NJ; j++)
            wmma::store_matrix_sync(cbuf + (i*16)*CLD + j*16, cf[i][j], CLD, wmma::mem_row_major);
    __syncwarp();
    const int ncol = n0 + wn*32 + lane;
    const float bv = bias ? bias[ncol] : 0.0f;
    const float gv = (EPI == 1) ? g_ada[g_off + ncol] : 0.0f;
#pragma unroll
    for (int r = 0; r < WTM; r++) {
        float v = cbuf[r*CLD + lane] + bv;
        size_t oi = (size_t)(m0 + wm*WTM + r)*N + ncol;
        if (EPI == 0) {
            out[oi] = v;
        } else if (EPI == 1) {
            out[oi] = out[oi] + gv * v;
        } else {
            float tn = tanhf(0.7978845608028654f*(v + 0.044715f*v*v*v));
            out[oi] = rtf(0.5f*v*(1.0f + tn));      // pre-round: fc2's A operand
        }
    }
}

// ---------------- fused flash attention: all smem tiles pre-rounded to tf32 ----------------
#define FLD  48
#define FLDS 68

__global__ void __launch_bounds__(128) k_flash() {
    extern __shared__ __align__(16) float fs[];
    float* sQ = fs;                 // 64 x 48
    float* sK = fs + 3072;          // 64 x 48
    float* sV = fs + 6144;          // 64 x 48
    float* sO = fs + 9216;          // 64 x 48
    float* sS = fs + 12288;         // 64 x 68 (64 cols used)
    float* sM = fs + 16640;         // 64
    float* sL = fs + 16704;         // 64

    const int tid  = threadIdx.x;   // 128
    const int warp = tid >> 5;
    const int qt = blockIdx.x, hh = blockIdx.y;
    const int l0 = qt*64;
    const float scale = 0.14433756729740643f;   // 48^-0.5
    const int rr = tid >> 1, hf = tid & 1;

    // load scaled Q tile (64 x 48), rounded to tf32
#pragma unroll
    for (int i = 0; i < 6; i++) {
        int e = tid + i*128;
        int r = e/12, c4 = e%12;
        float4 v = *(const float4*)&g_qkv[(size_t)(l0+r)*(3*EE) + hh*144 + c4*4];
        v.x = rtf(v.x*scale); v.y = rtf(v.y*scale); v.z = rtf(v.z*scale); v.w = rtf(v.w*scale);
        *(float4*)&sQ[r*FLD + c4*4] = v;
    }
    for (int i = tid; i < 64*FLD; i += 128) sO[i] = 0.0f;
    if (tid < 64) { sM[tid] = -1e30f; sL[tid] = 0.0f; }

    // register prefetch of K/V tile 0 (64 rows)
    float4 pk[6], pv[6];
#pragma unroll
    for (int i = 0; i < 6; i++) {
        int e = tid + i*128;
        int r = e/12, c4 = e%12;
        pk[i] = *(const float4*)&g_qkv[(size_t)r*(3*EE) + hh*144 + 48 + c4*4];
        pv[i] = *(const float4*)&g_qkv[(size_t)r*(3*EE) + hh*144 + 96 + c4*4];
    }

    for (int mt = 0; mt < 16; mt++) {
        const int m0 = mt*64;
        __syncthreads();               // protects sK/sV reuse (+ init on iter 0)
#pragma unroll
        for (int i = 0; i < 6; i++) {
            int e = tid + i*128;
            int r = e/12, c4 = e%12;
            float4 kk4 = pk[i], vv4 = pv[i];
            kk4.x=rtf(kk4.x); kk4.y=rtf(kk4.y); kk4.z=rtf(kk4.z); kk4.w=rtf(kk4.w);
            vv4.x=rtf(vv4.x); vv4.y=rtf(vv4.y); vv4.z=rtf(vv4.z); vv4.w=rtf(vv4.w);
            *(float4*)&sK[r*FLD + c4*4] = kk4;
            *(float4*)&sV[r*FLD + c4*4] = vv4;
        }
        __syncthreads();
        // prefetch next tile (overlaps with S/softmax/PV)
        if (mt < 15) {
            const int mn = m0 + 64;
#pragma unroll
            for (int i = 0; i < 6; i++) {
                int e = tid + i*128;
                int r = e/12, c4 = e%12;
                pk[i] = *(const float4*)&g_qkv[(size_t)(mn+r)*(3*EE) + hh*144 + 48 + c4*4];
                pv[i] = *(const float4*)&g_qkv[(size_t)(mn+r)*(3*EE) + hh*144 + 96 + c4*4];
            }
        }
        // S = Q @ K^T : warp handles rows warp*16..+15, cols 0..63
#pragma unroll
        for (int nt = 0; nt < 4; nt++) {
            wmma::fragment<wmma::accumulator,16,16,8,float> sc;
            wmma::fill_fragment(sc, 0.0f);
#pragma unroll
            for (int k = 0; k < 6; k++) {
                wmma::fragment<wmma::matrix_a,16,16,8,wmma::precision::tf32,wmma::row_major> af;
                wmma::fragment<wmma::matrix_b,16,16,8,wmma::precision::tf32,wmma::col_major> bf;
                wmma::load_matrix_sync(af, sQ + warp*16*FLD + k*8, FLD);
                wmma::load_matrix_sync(bf, sK + nt*16*FLD + k*8, FLD);
                wmma::mma_sync(sc, af, bf, sc);
            }
            wmma::store_matrix_sync(sS + warp*16*FLDS + nt*16, sc, FLDS, wmma::mem_row_major);
        }
        __syncthreads();
        // bias add + online softmax: 2 threads per row, 32 cols each
        {
            const int c0 = hf*32;
            const __nv_bfloat16* bp = &g_bh[((size_t)hh << 20) + ((size_t)(l0+rr) << 10) + m0 + c0];
            float* srow = sS + rr*FLDS + c0;
            float v[32];
            float mloc = -1e30f;
#pragma unroll
            for (int c = 0; c < 32; c++) {
                v[c] = srow[c] + __bfloat162float(bp[c]);
                mloc = fmaxf(mloc, v[c]);
            }
            mloc = fmaxf(mloc, __shfl_xor_sync(0xffffffffu, mloc, 1));
            float mprev = sM[rr];
            float mnew  = fmaxf(mprev, mloc);
            float sum = 0.f;
#pragma unroll
            for (int c = 0; c < 32; c++) {
                float p = __expf(v[c] - mnew);
                srow[c] = rtf(p);          // P pre-rounded for the PV mma
                sum += p;
            }
            sum += __shfl_xor_sync(0xffffffffu, sum, 1);
            float factor = __expf(mprev - mnew);
            if (hf == 0) { sM[rr] = mnew; sL[rr] = sL[rr]*factor + sum; }
            float* orow = sO + rr*FLD + hf*24;
#pragma unroll
            for (int c = 0; c < 24; c++) orow[c] *= factor;
        }
        __syncthreads();
        // O += P(64x64) @ V(64x48)
        {
            wmma::fragment<wmma::matrix_a,16,16,8,wmma::precision::tf32,wmma::row_major> pa[8];
#pragma unroll
            for (int kk = 0; kk < 8; kk++)
                wmma::load_matrix_sync(pa[kk], sS + warp*16*FLDS + kk*8, FLDS);
#pragma unroll
            for (int j = 0; j < 3; j++) {
                wmma::fragment<wmma::accumulator,16,16,8,float> of;
                wmma::load_matrix_sync(of, sO + warp*16*FLD + j*16, FLD, wmma::mem_row_major);
#pragma unroll
                for (int kk = 0; kk < 8; kk++) {
                    wmma::fragment<wmma::matrix_b,16,16,8,wmma::precision::tf32,wmma::row_major> vb;
                    wmma::load_matrix_sync(vb, sV + kk*8*FLD + j*16, FLD);
                    wmma::mma_sync(of, pa[kk], vb, of);
                }
                wmma::store_matrix_sync(sO + warp*16*FLD + j*16, of, FLD, wmma::mem_row_major);
            }
        }
    }
    __syncthreads();
    // normalize + write y[l, h*48+c] (rounded: y is the A operand of o-proj)
    {
        float inv = 1.0f / sL[rr];
        const float* orow = sO + rr*FLD + hf*24;
        float* dst = g_y + (size_t)(l0+rr)*EE + hh*HDIM + hf*24;
#pragma unroll
        for (int c = 0; c < 24; c++) dst[c] = rtf(orow[c]*inv);
    }
}

// ---------------- driver ----------------
static const int SM_BIG   = 2*(128+64)*GLD*4;   // 55296 B  (2-stage 128x64) -> 3 CTA/SM
static const int SM_SMALL = 2*(64+64)*GLD*4;    // 36864 B  (2-stage 64x64)  -> 3 CTA/SM (reg-capped)
static const int SM_FLASH = 16768*4;            // 67072 B

extern "C" void kernel_launch(void* const* d_in, const int* in_sizes, int n_in,
                              void* d_out, int out_size) {
    const float* z    = (const float*)d_in[0];
    const float* t    = (const float*)d_in[1];
    const float* bias = (const float*)d_in[2];
    const float* ln_g = (const float*)d_in[3];
    const float* ln_b = (const float*)d_in[4];
    const float* p2sw = (const float*)d_in[5];
    const float* t0w  = (const float*)d_in[6];
    const float* t0b  = (const float*)d_in[7];
    const float* t2w  = (const float*)d_in[8];
    const float* t2b  = (const float*)d_in[9];
    const float* pw   = (const float*)d_in[10];
    const float* ow   = (const float*)d_in[11];
    const float* ob   = (const float*)d_in[12];
    const float* aw   = (const float*)d_in[13];
    const float* ab   = (const float*)d_in[14];
    const float* f1w  = (const float*)d_in[15];
    const float* f1b  = (const float*)d_in[16];
    const float* f2w  = (const float*)d_in[17];
    const float* f2b  = (const float*)d_in[18];
    const float* faw  = (const float*)d_in[19];
    const float* fab  = (const float*)d_in[20];
    const float* fw   = (const float*)d_in[21];
    const float* fb   = (const float*)d_in[22];

    float *px, *ph, *pq, *py, *pm;
    cudaGetSymbolAddress((void**)&px, g_x);
    cudaGetSymbolAddress((void**)&ph, g_h);
    cudaGetSymbolAddress((void**)&pq, g_qkv);
    cudaGetSymbolAddress((void**)&py, g_y);
    cudaGetSymbolAddress((void**)&pm, g_mlp);

    cudaFuncSetAttribute(k_gemm<0,128,32>, cudaFuncAttributeMaxDynamicSharedMemorySize, SM_BIG);
    cudaFuncSetAttribute(k_gemm<2,128,32>, cudaFuncAttributeMaxDynamicSharedMemorySize, SM_BIG);
    cudaFuncSetAttribute(k_gemm<0,64,16>,  cudaFuncAttributeMaxDynamicSharedMemorySize, SM_SMALL);
    cudaFuncSetAttribute(k_gemm<1,64,16>,  cudaFuncAttributeMaxDynamicSharedMemorySize, SM_SMALL);
    cudaFuncSetAttribute(k_flash,          cudaFuncAttributeMaxDynamicSharedMemorySize, SM_FLASH);

    // ---- ncu captures our 4th launch -> slot 4 = qkv GEMM ----
    k_timeAll<<<96, 256>>>(t, t0w, t0b, t2w, t2b);              // 1
    k_ada<<<4800, 256>>>(aw, ab, faw, fab);                     // 2
    k_lnmod<<<1024, 256>>>(z, 0, EE, ph);                       // 3 (block-0 LN reads z directly)
    k_gemm<0,128,32><<<dim3(36, 8), 256, SM_BIG>>>(             // 4  <-- profiled next round
        ph, pw, nullptr, 0, pq, LL, 3*EE, EE);
    k_prep<<<1, 128>>>(ln_g, ln_b, p2sw);                       // 5
    k_bias<<<4096, 256>>>(bias);                                // 6
    k_copy<<<768, 1024>>>(z);                                   // 7
    k_flash<<<dim3(16, 16), 128, SM_FLASH>>>();                 // 8
    k_gemm<1,64,16><<<dim3(12, 16), 256, SM_SMALL>>>(py, ow, ob, 2*EE, px, LL, EE, EE);
    k_lnmod<<<1024, 256>>>(px, 3*EE, 4*EE, ph);
    k_gemm<2,128,32><<<dim3(48, 8), 256, SM_BIG>>>(ph, f1w, f1b, 0, pm, LL, MLPD, EE);
    k_gemm<1,64,16><<<dim3(12, 16), 256, SM_SMALL>>>(pm, f2w, f2b, 5*EE, px, LL, EE, MLPD);

    for (int d = 1; d < NDEPTH; d++) {
        const int base = d*6*EE;
        // attention branch
        k_lnmod<<<1024, 256>>>(px, base, base + EE, ph);
        k_gemm<0,128,32><<<dim3(36, 8), 256, SM_BIG>>>(ph, pw + (size_t)d*3*EE*EE, nullptr, 0,
                                                       pq, LL, 3*EE, EE);
        k_flash<<<dim3(16, 16), 128, SM_FLASH>>>();
        k_gemm<1,64,16><<<dim3(12, 16), 256, SM_SMALL>>>(py, ow + (size_t)d*EE*EE, ob + d*EE, base + 2*EE,
                                                         px, LL, EE, EE);
        // MLP branch
        k_lnmod<<<1024, 256>>>(px, base + 3*EE, base + 4*EE, ph);
        k_gemm<2,128,32><<<dim3(48, 8), 256, SM_BIG>>>(ph, f1w + (size_t)d*MLPD*EE, f1b + d*MLPD, 0,
                                                       pm, LL, MLPD, EE);
        k_gemm<1,64,16><<<dim3(12, 16), 256, SM_SMALL>>>(pm, f2w + (size_t)d*EE*MLPD, f2b + d*EE, base + 5*EE,
                                                         px, LL, EE, MLPD);
    }
    // final
    const int foff = NDEPTH*6*EE;
    k_lnmod<<<1024, 256>>>(px, foff, foff + EE, ph);
    k_gemm<0,64,16><<<dim3(12, 16), 256, SM_SMALL>>>(ph, fw, fb, 0, (float*)d_out, LL, EE, EE);
}

// round 17
// speedup vs baseline: 1.1063x; 1.0088x over previous
#include <cuda_runtime.h>
#include <cuda_bf16.h>
#include <mma.h>
#include <cmath>

using namespace nvcuda;

#define LL     1024
#define EE     768
#define PPD    128
#define HH     16
#define HDIM   48
#define NDEPTH 8
#define MLPD   3072
#define NFREQ  256

// pre-rounded weight scratch layout (floats)
#define PW_SZ  (NDEPTH*3*EE*EE)          // 14155776
#define OW_SZ  (NDEPTH*EE*EE)            //  4718592
#define F1_SZ  (NDEPTH*MLPD*EE)          // 18874368
#define F2_SZ  (NDEPTH*EE*MLPD)          // 18874368
#define FW_SZ  (EE*EE)                   //   589824
#define PW_OFF 0
#define OW_OFF (PW_OFF + PW_SZ)
#define F1_OFF (OW_OFF + OW_SZ)
#define F2_OFF (F1_OFF + F1_SZ)
#define FW_OFF (F2_OFF + F2_SZ)
#define WR_TOT (FW_OFF + FW_SZ)          // 57212928 floats = 228.9 MB

// ---------------- device-global scratch (no allocations allowed) ----------------
__device__ __align__(16) float g_x[LL*EE];
__device__ __align__(16) float g_h[LL*EE];
__device__ __align__(16) float g_qkv[LL*3*EE];
__device__ __align__(16) float g_y[LL*EE];
__device__ __align__(16) float g_mlp[LL*MLPD];
__device__ __align__(16) __nv_bfloat16 g_bh[(size_t)HH*LL*LL];   // 32 MB, [h][l][m]
__device__ __align__(16) float g_wr[WR_TOT];                     // tf32-rounded weights
__device__ float g_cs[EE];
__device__ float g_ada[NDEPTH*6*EE + 2*EE];
__device__ float g_Apw[HH*PPD];
__device__ float g_Spw[HH];
__device__ float g_Cpw[HH];

__device__ __forceinline__ void cp16(float* s, const float* g) {
    unsigned sa = (unsigned)__cvta_generic_to_shared(s);
    asm volatile("cp.async.cg.shared.global [%0], [%1], 16;\n" :: "r"(sa), "l"(g));
}
#define CP_COMMIT() asm volatile("cp.async.commit_group;\n" ::: "memory")
#define CP_WAIT0()  asm volatile("cp.async.wait_group 0;\n" ::: "memory")
#define CP_WAIT1()  asm volatile("cp.async.wait_group 1;\n" ::: "memory")

// round to tf32 (same op the wmma cvt loops used to do)
__device__ __forceinline__ float rtf(float x) { return wmma::__float_to_tf32(x); }

// ---------------- init ----------------
__global__ void k_copy(const float* __restrict__ z) {
    int i = blockIdx.x*1024 + threadIdx.x;
    g_x[i] = z[i];
}

// round all weight matrices to tf32 into g_wr (B operands of every GEMM)
__global__ void __launch_bounds__(256) k_round(const float* __restrict__ pw,
                                               const float* __restrict__ ow,
                                               const float* __restrict__ f1w,
                                               const float* __restrict__ f2w,
                                               const float* __restrict__ fw) {
    size_t i = ((size_t)blockIdx.x*256 + threadIdx.x)*4;
    if (i >= WR_TOT) return;
    const float* src; size_t off;
    if      (i < OW_OFF) { src = pw;  off = i; }
    else if (i < F1_OFF) { src = ow;  off = i - OW_OFF; }
    else if (i < F2_OFF) { src = f1w; off = i - F1_OFF; }
    else if (i < FW_OFF) { src = f2w; off = i - F2_OFF; }
    else                 { src = fw;  off = i - FW_OFF; }
    float4 v = *(const float4*)(src + off);
    v.x = rtf(v.x); v.y = rtf(v.y); v.z = rtf(v.z); v.w = rtf(v.w);
    *(float4*)&g_wr[i] = v;
}

__global__ void k_prep(const float* __restrict__ g, const float* __restrict__ beta,
                       const float* __restrict__ w) {
    const int p = threadIdx.x; // 128
    for (int h = 0; h < HH; h++)
        g_Apw[h*PPD + p] = g[p] * w[h*PPD + p];
    if (p < HH) {
        float s = 0.f, c = 0.f;
        for (int q = 0; q < PPD; q++) {
            s += g[q]    * w[p*PPD + q];
            c += beta[q] * w[p*PPD + q];
        }
        g_Spw[p] = s; g_Cpw[p] = c;
    }
}

// ---------------- bias LN + head projection: 512 MB read, one thread per row ----------------
__global__ void __launch_bounds__(256) k_bias(const float* __restrict__ bias) {
    __shared__ __align__(16) float sA[HH*PPD];
    __shared__ float sSh[HH], sCh[HH];
    const int tid = threadIdx.x;
    for (int i = tid; i < HH*PPD; i += 256) sA[i] = g_Apw[i];
    if (tid < HH) { sSh[tid] = g_Spw[tid]; sCh[tid] = g_Cpw[tid]; }
    __syncthreads();
    const int row = blockIdx.x*256 + tid;      // row = l*1024 + m
    const float* xr = bias + (size_t)row*PPD;
    float acc[HH];
#pragma unroll
    for (int h = 0; h < HH; h++) acc[h] = 0.f;
    float s = 0.f, ss = 0.f;
#pragma unroll
    for (int ch = 0; ch < 4; ch++) {
        float4 xv[8];
#pragma unroll
        for (int j = 0; j < 8; j++) xv[j] = *(const float4*)&xr[ch*32 + j*4];
#pragma unroll
        for (int j = 0; j < 8; j++) {
            s  += xv[j].x + xv[j].y + xv[j].z + xv[j].w;
            ss += xv[j].x*xv[j].x + xv[j].y*xv[j].y + xv[j].z*xv[j].z + xv[j].w*xv[j].w;
        }
#pragma unroll
        for (int h = 0; h < HH; h++) {
            const float* ar = &sA[h*PPD + ch*32];
            float a0 = 0.f;
#pragma unroll
            for (int j = 0; j < 8; j++) {
                float4 av = *(const float4*)&ar[j*4];
                a0 += xv[j].x*av.x + xv[j].y*av.y + xv[j].z*av.z + xv[j].w*av.w;
            }
            acc[h] += a0;
        }
    }
    const float mu   = s * (1.0f/PPD);
    const float rstd = rsqrtf(ss*(1.0f/PPD) - mu*mu + 1e-6f);
    const int l = row >> 10, m = row & 1023;
#pragma unroll
    for (int h = 0; h < HH; h++) {
        float v = rstd*(acc[h] - mu*sSh[h]) + sCh[h];
        g_bh[((size_t)h << 20) + ((size_t)l << 10) + m] = __float2bfloat16(v);
    }
}

// ---------------- time embedding chain, fused ----------------
__global__ void __launch_bounds__(256) k_timeAll(const float* __restrict__ t,
                                                 const float* __restrict__ t0_w,
                                                 const float* __restrict__ t0_b,
                                                 const float* __restrict__ t2_w,
                                                 const float* __restrict__ t2_b) {
    __shared__ float emb[NFREQ];
    __shared__ float cp[EE];
    const int tid = threadIdx.x;  // 256
    {
        int i = tid & 127;
        float f   = expf(-9.210340371976184f * (float)i / 128.0f);
        float arg = t[0] * f;
        emb[tid] = (tid < 128) ? cosf(arg) : sinf(arg);
    }
    __syncthreads();
#pragma unroll
    for (int rep = 0; rep < 3; rep++) {
        const int j = tid + rep*256;
        const float* w = t0_w + (size_t)j*NFREQ;
        float a = t0_b[j];
#pragma unroll
        for (int i = 0; i < 64; i++) {
            float4 wv = *(const float4*)&w[i*4];
            a += emb[i*4]*wv.x + emb[i*4+1]*wv.y + emb[i*4+2]*wv.z + emb[i*4+3]*wv.w;
        }
        cp[j] = a / (1.f + expf(-a));
    }
    __syncthreads();
    const int warp = tid >> 5, lane = tid & 31;
    const int j = blockIdx.x*8 + warp;          // grid 96 -> 768 rows
    const float* w = t2_w + (size_t)j*EE;
    float acc = 0.f;
#pragma unroll
    for (int i = 0; i < 24; i++) acc += cp[lane + i*32] * w[lane + i*32];
#pragma unroll
    for (int o = 16; o > 0; o >>= 1) acc += __shfl_xor_sync(0xffffffffu, acc, o);
    if (lane == 0) {
        float a = acc + t2_b[j];
        g_cs[j] = a / (1.f + expf(-a));
    }
}

// all adaLN vectors, one warp per row
__global__ void k_ada(const float* __restrict__ aw, const float* __restrict__ ab,
                      const float* __restrict__ fw, const float* __restrict__ fb) {
    const int gw   = (blockIdx.x*blockDim.x + threadIdx.x) >> 5;
    const int lane = threadIdx.x & 31;
    const int total = NDEPTH*6*EE + 2*EE;
    if (gw >= total) return;
    const float* wrow; float b;
    if (gw < NDEPTH*6*EE) { wrow = aw + (size_t)gw*EE; b = ab[gw]; }
    else { int r = gw - NDEPTH*6*EE; wrow = fw + (size_t)r*EE; b = fb[r]; }
    float acc = 0.f;
    for (int i = lane; i < EE; i += 32) acc += g_cs[i]*wrow[i];
#pragma unroll
    for (int o = 16; o > 0; o >>= 1) acc += __shfl_xor_sync(0xffffffffu, acc, o);
    if (lane == 0) g_ada[gw] = acc + b;
}

// ---------------- LayerNorm + adaLN modulation (output pre-rounded to tf32) ----------------
__global__ void __launch_bounds__(256) k_lnmod(const float* __restrict__ x,
                                               int sh_off, int sc_off,
                                               float* __restrict__ out) {
    const int row = blockIdx.x, tid = threadIdx.x;
    const float* xr = x + (size_t)row*EE;
    float v0 = xr[tid], v1 = xr[tid+256], v2 = xr[tid+512];
    float s  = v0 + v1 + v2;
    float ss = v0*v0 + v1*v1 + v2*v2;
    __shared__ float rs[8], rss[8];
#pragma unroll
    for (int o = 16; o > 0; o >>= 1) {
        s  += __shfl_xor_sync(0xffffffffu, s,  o);
        ss += __shfl_xor_sync(0xffffffffu, ss, o);
    }
    if ((tid & 31) == 0) { rs[tid>>5] = s; rss[tid>>5] = ss; }
    __syncthreads();
    float st = 0.f, sst = 0.f;
#pragma unroll
    for (int i = 0; i < 8; i++) { st += rs[i]; sst += rss[i]; }
    const float mu   = st * (1.0f/EE);
    const float rstd = rsqrtf(sst*(1.0f/EE) - mu*mu + 1e-6f);
    const float* sh = g_ada + sh_off;
    const float* sc = g_ada + sc_off;
    float* orow = out + (size_t)row*EE;
    orow[tid]     = rtf((v0-mu)*rstd*(1.f+sc[tid])     + sh[tid]);
    orow[tid+256] = rtf((v1-mu)*rstd*(1.f+sc[tid+256]) + sh[tid+256]);
    orow[tid+512] = rtf((v2-mu)*rstd*(1.f+sc[tid+512]) + sh[tid+512]);
}

// ---------------- tf32 wmma GEMM, cp.async 3-stage, ONE barrier/chunk, no cvt ----------------
// Both operands pre-rounded to tf32 (A by producer kernels, W by k_round).
// EPI 0: out=acc+bias  EPI 1: out += g_ada[g_off+n]*(acc+bias)  EPI 2: out = rtf(gelu(acc+bias))
#define GBK 32
#define GLD 36

template<int BM, int AF4, int BF4>
__device__ __forceinline__ void g_issue(float* stage, const float* A, const float* W,
                                        int m0, int n0, int K, int k0, int tid) {
    float* sA = stage;
    float* sB = stage + BM*GLD;
#pragma unroll
    for (int i = 0; i < AF4; i++) {
        int f = tid + i*256;
        cp16(&sA[(f>>3)*GLD + ((f&7)<<2)], &A[(size_t)(m0 + (f>>3))*K + k0 + ((f&7)<<2)]);
    }
#pragma unroll
    for (int i = 0; i < BF4; i++) {
        int f = tid + i*256;
        cp16(&sB[(f>>3)*GLD + ((f&7)<<2)], &W[(size_t)(n0 + (f>>3))*K + k0 + ((f&7)<<2)]);
    }
    CP_COMMIT();
}

template<int EPI, int BM, int WTM>
__global__ void __launch_bounds__(256) k_gemm(
        const float* __restrict__ A, const float* __restrict__ W,
        const float* __restrict__ bias, int g_off,
        float* __restrict__ out, int M, int N, int K) {
    constexpr int BN  = 64;
    constexpr int WMC = BM/WTM;
    constexpr int MI  = WTM/16;
    constexpr int NJ  = 2;
    constexpr int STG = (BM+BN)*GLD;
    constexpr int AF4 = BM*8/256, BF4 = BN*8/256;
    constexpr int CLD = 36;

    extern __shared__ __align__(16) float smem[];
    const int tid = threadIdx.x, warp = tid >> 5, lane = tid & 31;
    const int wm = warp % WMC, wn = warp / WMC;
    const int m0 = blockIdx.y * BM;
    const int n0 = blockIdx.x * BN;

    wmma::fragment<wmma::accumulator,16,16,8,float> cf[MI][NJ];
#pragma unroll
    for (int i = 0; i < MI; i++)
#pragma unroll
        for (int j = 0; j < NJ; j++) wmma::fill_fragment(cf[i][j], 0.0f);

    const int nch = K / GBK;
    g_issue<BM,AF4,BF4>(smem,       A, W, m0, n0, K, 0,   tid);
    g_issue<BM,AF4,BF4>(smem + STG, A, W, m0, n0, K, GBK, tid);

    for (int ch = 0; ch < nch; ch++) {
        if (ch == nch-1) { CP_WAIT0(); } else { CP_WAIT1(); }
        __syncthreads();
        float* sA = smem + (ch % 3)*STG;
        float* sB = sA + BM*GLD;
#pragma unroll
        for (int kk = 0; kk < 4; kk++) {
            wmma::fragment<wmma::matrix_a,16,16,8,wmma::precision::tf32,wmma::row_major> af[MI];
            wmma::fragment<wmma::matrix_b,16,16,8,wmma::precision::tf32,wmma::col_major> bf[NJ];
#pragma unroll
            for (int i = 0; i < MI; i++)
                wmma::load_matrix_sync(af[i], sA + (wm*WTM + i*16)*GLD + kk*8, GLD);
#pragma unroll
            for (int j = 0; j < NJ; j++)
                wmma::load_matrix_sync(bf[j], sB + (wn*32 + j*16)*GLD + kk*8, GLD);
#pragma unroll
            for (int i = 0; i < MI; i++)
#pragma unroll
                for (int j = 0; j < NJ; j++) wmma::mma_sync(cf[i][j], af[i], bf[j], cf[i][j]);
        }
        if (ch + 2 < nch)
            g_issue<BM,AF4,BF4>(smem + ((ch+2) % 3)*STG, A, W, m0, n0, K, (ch+2)*GBK, tid);
    }
    __syncthreads();
    // epilogue: stage per-warp WTM x 32 tile in smem
    float* cbuf = smem + warp*(WTM*CLD);
#pragma unroll
    for (int i = 0; i < MI; i++)
#pragma unroll
        for (int j = 0; j < NJ; j++)
            wmma::store_matrix_sync(cbuf + (i*16)*CLD + j*16, cf[i][j], CLD, wmma::mem_row_major);
    __syncwarp();
    const int ncol = n0 + wn*32 + lane;
    const float bv = bias ? bias[ncol] : 0.0f;
    const float gv = (EPI == 1) ? g_ada[g_off + ncol] : 0.0f;
#pragma unroll
    for (int r = 0; r < WTM; r++) {
        float v = cbuf[r*CLD + lane] + bv;
        size_t oi = (size_t)(m0 + wm*WTM + r)*N + ncol;
        if (EPI == 0) {
            out[oi] = v;
        } else if (EPI == 1) {
            out[oi] = out[oi] + gv * v;
        } else {
            float tn = tanhf(0.7978845608028654f*(v + 0.044715f*v*v*v));
            out[oi] = rtf(0.5f*v*(1.0f + tn));      // pre-round: fc2's A operand
        }
    }
}

// ---------------- fused flash attention: all smem tiles pre-rounded to tf32 ----------------
#define FLD  48
#define FLDS 68

__global__ void __launch_bounds__(128) k_flash() {
    extern __shared__ __align__(16) float fs[];
    float* sQ = fs;                 // 64 x 48
    float* sK = fs + 3072;          // 64 x 48
    float* sV = fs + 6144;          // 64 x 48
    float* sO = fs + 9216;          // 64 x 48
    float* sS = fs + 12288;         // 64 x 68 (64 cols used)
    float* sM = fs + 16640;         // 64
    float* sL = fs + 16704;         // 64

    const int tid  = threadIdx.x;   // 128
    const int warp = tid >> 5;
    const int qt = blockIdx.x, hh = blockIdx.y;
    const int l0 = qt*64;
    const float scale = 0.14433756729740643f;   // 48^-0.5
    const int rr = tid >> 1, hf = tid & 1;

    // load scaled Q tile (64 x 48), rounded to tf32
#pragma unroll
    for (int i = 0; i < 6; i++) {
        int e = tid + i*128;
        int r = e/12, c4 = e%12;
        float4 v = *(const float4*)&g_qkv[(size_t)(l0+r)*(3*EE) + hh*144 + c4*4];
        v.x = rtf(v.x*scale); v.y = rtf(v.y*scale); v.z = rtf(v.z*scale); v.w = rtf(v.w*scale);
        *(float4*)&sQ[r*FLD + c4*4] = v;
    }
    for (int i = tid; i < 64*FLD; i += 128) sO[i] = 0.0f;
    if (tid < 64) { sM[tid] = -1e30f; sL[tid] = 0.0f; }

    // register prefetch of K/V tile 0 (64 rows)
    float4 pk[6], pv[6];
#pragma unroll
    for (int i = 0; i < 6; i++) {
        int e = tid + i*128;
        int r = e/12, c4 = e%12;
        pk[i] = *(const float4*)&g_qkv[(size_t)r*(3*EE) + hh*144 + 48 + c4*4];
        pv[i] = *(const float4*)&g_qkv[(size_t)r*(3*EE) + hh*144 + 96 + c4*4];
    }

    for (int mt = 0; mt < 16; mt++) {
        const int m0 = mt*64;
        __syncthreads();               // protects sK/sV reuse (+ init on iter 0)
#pragma unroll
        for (int i = 0; i < 6; i++) {
            int e = tid + i*128;
            int r = e/12, c4 = e%12;
            float4 kk4 = pk[i], vv4 = pv[i];
            kk4.x=rtf(kk4.x); kk4.y=rtf(kk4.y); kk4.z=rtf(kk4.z); kk4.w=rtf(kk4.w);
            vv4.x=rtf(vv4.x); vv4.y=rtf(vv4.y); vv4.z=rtf(vv4.z); vv4.w=rtf(vv4.w);
            *(float4*)&sK[r*FLD + c4*4] = kk4;
            *(float4*)&sV[r*FLD + c4*4] = vv4;
        }
        __syncthreads();
        // prefetch next tile (overlaps with S/softmax/PV)
        if (mt < 15) {
            const int mn = m0 + 64;
#pragma unroll
            for (int i = 0; i < 6; i++) {
                int e = tid + i*128;
                int r = e/12, c4 = e%12;
                pk[i] = *(const float4*)&g_qkv[(size_t)(mn+r)*(3*EE) + hh*144 + 48 + c4*4];
                pv[i] = *(const float4*)&g_qkv[(size_t)(mn+r)*(3*EE) + hh*144 + 96 + c4*4];
            }
        }
        // S = Q @ K^T : warp handles rows warp*16..+15, cols 0..63
#pragma unroll
        for (int nt = 0; nt < 4; nt++) {
            wmma::fragment<wmma::accumulator,16,16,8,float> sc;
            wmma::fill_fragment(sc, 0.0f);
#pragma unroll
            for (int k = 0; k < 6; k++) {
                wmma::fragment<wmma::matrix_a,16,16,8,wmma::precision::tf32,wmma::row_major> af;
                wmma::fragment<wmma::matrix_b,16,16,8,wmma::precision::tf32,wmma::col_major> bf;
                wmma::load_matrix_sync(af, sQ + warp*16*FLD + k*8, FLD);
                wmma::load_matrix_sync(bf, sK + nt*16*FLD + k*8, FLD);
                wmma::mma_sync(sc, af, bf, sc);
            }
            wmma::store_matrix_sync(sS + warp*16*FLDS + nt*16, sc, FLDS, wmma::mem_row_major);
        }
        __syncthreads();
        // bias add + online softmax: 2 threads per row, 32 cols each
        {
            const int c0 = hf*32;
            const __nv_bfloat16* bp = &g_bh[((size_t)hh << 20) + ((size_t)(l0+rr) << 10) + m0 + c0];
            float* srow = sS + rr*FLDS + c0;
            float v[32];
            float mloc = -1e30f;
#pragma unroll
            for (int c = 0; c < 32; c++) {
                v[c] = srow[c] + __bfloat162float(bp[c]);
                mloc = fmaxf(mloc, v[c]);
            }
            mloc = fmaxf(mloc, __shfl_xor_sync(0xffffffffu, mloc, 1));
            float mprev = sM[rr];
            float mnew  = fmaxf(mprev, mloc);
            float sum = 0.f;
#pragma unroll
            for (int c = 0; c < 32; c++) {
                float p = __expf(v[c] - mnew);
                srow[c] = rtf(p);          // P pre-rounded for the PV mma
                sum += p;
            }
            sum += __shfl_xor_sync(0xffffffffu, sum, 1);
            float factor = __expf(mprev - mnew);
            if (hf == 0) { sM[rr] = mnew; sL[rr] = sL[rr]*factor + sum; }
            float* orow = sO + rr*FLD + hf*24;
#pragma unroll
            for (int c = 0; c < 24; c++) orow[c] *= factor;
        }
        __syncthreads();
        // O += P(64x64) @ V(64x48)
        {
            wmma::fragment<wmma::matrix_a,16,16,8,wmma::precision::tf32,wmma::row_major> pa[8];
#pragma unroll
            for (int kk = 0; kk < 8; kk++)
                wmma::load_matrix_sync(pa[kk], sS + warp*16*FLDS + kk*8, FLDS);
#pragma unroll
            for (int j = 0; j < 3; j++) {
                wmma::fragment<wmma::accumulator,16,16,8,float> of;
                wmma::load_matrix_sync(of, sO + warp*16*FLD + j*16, FLD, wmma::mem_row_major);
#pragma unroll
                for (int kk = 0; kk < 8; kk++) {
                    wmma::fragment<wmma::matrix_b,16,16,8,wmma::precision::tf32,wmma::row_major> vb;
                    wmma::load_matrix_sync(vb, sV + kk*8*FLD + j*16, FLD);
                    wmma::mma_sync(of, pa[kk], vb, of);
                }
                wmma::store_matrix_sync(sO + warp*16*FLD + j*16, of, FLD, wmma::mem_row_major);
            }
        }
    }
    __syncthreads();
    // normalize + write y[l, h*48+c] (rounded: y is the A operand of o-proj)
    {
        float inv = 1.0f / sL[rr];
        const float* orow = sO + rr*FLD + hf*24;
        float* dst = g_y + (size_t)(l0+rr)*EE + hh*HDIM + hf*24;
#pragma unroll
        for (int c = 0; c < 24; c++) dst[c] = rtf(orow[c]*inv);
    }
}

// ---------------- driver ----------------
static const int SM_BIG   = 3*(128+64)*GLD*4;   // 82944 B  (3-stage 128x64)
static const int SM_SMALL = 3*(64+64)*GLD*4;    // 55296 B  (3-stage 64x64)
static const int SM_FLASH = 16768*4;            // 67072 B

extern "C" void kernel_launch(void* const* d_in, const int* in_sizes, int n_in,
                              void* d_out, int out_size) {
    const float* z    = (const float*)d_in[0];
    const float* t    = (const float*)d_in[1];
    const float* bias = (const float*)d_in[2];
    const float* ln_g = (const float*)d_in[3];
    const float* ln_b = (const float*)d_in[4];
    const float* p2sw = (const float*)d_in[5];
    const float* t0w  = (const float*)d_in[6];
    const float* t0b  = (const float*)d_in[7];
    const float* t2w  = (const float*)d_in[8];
    const float* t2b  = (const float*)d_in[9];
    const float* pw   = (const float*)d_in[10];
    const float* ow   = (const float*)d_in[11];
    const float* ob   = (const float*)d_in[12];
    const float* aw   = (const float*)d_in[13];
    const float* ab   = (const float*)d_in[14];
    const float* f1w  = (const float*)d_in[15];
    const float* f1b  = (const float*)d_in[16];
    const float* f2w  = (const float*)d_in[17];
    const float* f2b  = (const float*)d_in[18];
    const float* faw  = (const float*)d_in[19];
    const float* fab  = (const float*)d_in[20];
    const float* fw   = (const float*)d_in[21];
    const float* fb   = (const float*)d_in[22];

    float *px, *ph, *pq, *py, *pm, *pwr;
    cudaGetSymbolAddress((void**)&px, g_x);
    cudaGetSymbolAddress((void**)&ph, g_h);
    cudaGetSymbolAddress((void**)&pq, g_qkv);
    cudaGetSymbolAddress((void**)&py, g_y);
    cudaGetSymbolAddress((void**)&pm, g_mlp);
    cudaGetSymbolAddress((void**)&pwr, g_wr);
    const float* pwr_pw = pwr + PW_OFF;
    const float* pwr_ow = pwr + OW_OFF;
    const float* pwr_f1 = pwr + F1_OFF;
    const float* pwr_f2 = pwr + F2_OFF;
    const float* pwr_fw = pwr + FW_OFF;

    cudaFuncSetAttribute(k_gemm<0,128,32>, cudaFuncAttributeMaxDynamicSharedMemorySize, SM_BIG);
    cudaFuncSetAttribute(k_gemm<2,128,32>, cudaFuncAttributeMaxDynamicSharedMemorySize, SM_BIG);
    cudaFuncSetAttribute(k_gemm<0,64,16>,  cudaFuncAttributeMaxDynamicSharedMemorySize, SM_SMALL);
    cudaFuncSetAttribute(k_gemm<1,64,16>,  cudaFuncAttributeMaxDynamicSharedMemorySize, SM_SMALL);
    cudaFuncSetAttribute(k_flash,          cudaFuncAttributeMaxDynamicSharedMemorySize, SM_FLASH);

    k_round<<<(WR_TOT/4 + 255)/256, 256>>>(pw, ow, f1w, f2w, fw);
    k_timeAll<<<96, 256>>>(t, t0w, t0b, t2w, t2b);
    k_ada<<<4800, 256>>>(aw, ab, faw, fab);
    k_lnmod<<<1024, 256>>>(z, 0, EE, ph);            // block-0 LN reads z directly
    k_gemm<0,128,32><<<dim3(36, 8), 256, SM_BIG>>>(ph, pwr_pw, nullptr, 0, pq, LL, 3*EE, EE);
    k_prep<<<1, 128>>>(ln_g, ln_b, p2sw);
    k_bias<<<4096, 256>>>(bias);
    k_copy<<<768, 1024>>>(z);
    k_flash<<<dim3(16, 16), 128, SM_FLASH>>>();
    k_gemm<1,64,16><<<dim3(12, 16), 256, SM_SMALL>>>(py, pwr_ow, ob, 2*EE, px, LL, EE, EE);
    k_lnmod<<<1024, 256>>>(px, 3*EE, 4*EE, ph);
    k_gemm<2,128,32><<<dim3(48, 8), 256, SM_BIG>>>(ph, pwr_f1, f1b, 0, pm, LL, MLPD, EE);
    k_gemm<1,64,16><<<dim3(12, 16), 256, SM_SMALL>>>(pm, pwr_f2, f2b, 5*EE, px, LL, EE, MLPD);

    for (int d = 1; d < NDEPTH; d++) {
        const int base = d*6*EE;
        // attention branch
        k_lnmod<<<1024, 256>>>(px, base, base + EE, ph);
        k_gemm<0,128,32><<<dim3(36, 8), 256, SM_BIG>>>(ph, pwr_pw + (size_t)d*3*EE*EE, nullptr, 0,
                                                       pq, LL, 3*EE, EE);
        k_flash<<<dim3(16, 16), 128, SM_FLASH>>>();
        k_gemm<1,64,16><<<dim3(12, 16), 256, SM_SMALL>>>(py, pwr_ow + (size_t)d*EE*EE, ob + d*EE, base + 2*EE,
                                                         px, LL, EE, EE);
        // MLP branch
        k_lnmod<<<1024, 256>>>(px, base + 3*EE, base + 4*EE, ph);
        k_gemm<2,128,32><<<dim3(48, 8), 256, SM_BIG>>>(ph, pwr_f1 + (size_t)d*MLPD*EE, f1b + d*MLPD, 0,
                                                       pm, LL, MLPD, EE);
        k_gemm<1,64,16><<<dim3(12, 16), 256, SM_SMALL>>>(pm, pwr_f2 + (size_t)d*EE*MLPD, f2b + d*EE, base + 5*EE,
                                                         px, LL, EE, MLPD);
    }
    // final
    const int foff = NDEPTH*6*EE;
    k_lnmod<<<1024, 256>>>(px, foff, foff + EE, ph);
    k_gemm<0,64,16><<<dim3(12, 16), 256, SM_SMALL>>>(ph, pwr_fw, fb, 0, (float*)d_out, LL, EE, EE);
}